// round 6
// baseline (speedup 1.0000x reference)
#include <cuda_runtime.h>
#include <cstdint>

// ===========================================================================
// AxisAttention via mma.sync tf32, k-permuted float2-fragment layout.
// 3xTF32 split precision for q/k projections and QK^T (256 thr, occ 2,
// K-chunk 16, warp tile 64x32); single-pass tf32 for v-proj, PV, out-proj.
// B=4, N=2048, D=DA=512.
// ===========================================================================

constexpr int BB  = 4;
constexpr int SEQ = 2048;
constexpr int DIM = 512;
constexpr float SCALE_F = 22.62741699796952f;  // sqrt(512), multiplied

constexpr size_t BND = (size_t)BB * SEQ * DIM;

// ---------------- device global scratch (no runtime allocation) -----------
__device__ float g_in_hi[2 * BND];     // [query ; key_value] split-hi
__device__ float g_in_lo[2 * BND];
__device__ float g_qk_hi[2 * BND];     // [q ; k] projections split-hi
__device__ float g_qk_lo[2 * BND];
__device__ float g_vt[(size_t)BB * DIM * SEQ];   // V^T per batch [DIM, SEQ]
__device__ float g_s[(size_t)BB * SEQ * SEQ];    // scores / probs
__device__ float g_o[BND];
__device__ float g_wqk_hi[2 * DIM * DIM];        // [Wq^T ; Wk^T]
__device__ float g_wqk_lo[2 * DIM * DIM];
__device__ float g_wvt[DIM * DIM];
__device__ float g_wot[DIM * DIM];

// ---------------- helpers ---------------------------------------------------
__device__ __forceinline__ uint32_t smem_u32(const void* p) {
    uint32_t a;
    asm("{ .reg .u64 t; cvta.to.shared.u64 t, %1; cvt.u32.u64 %0, t; }"
        : "=r"(a) : "l"(p));
    return a;
}
__device__ __forceinline__ float tf32_rna(float x) {
    uint32_t u;
    asm("cvt.rna.tf32.f32 %0, %1;" : "=r"(u) : "f"(x));
    return __uint_as_float(u);
}
__device__ __forceinline__ void cp16(uint32_t saddr, const void* g) {
    asm volatile("cp.async.cg.shared.global [%0], [%1], 16;"
                 :: "r"(saddr), "l"(g) : "memory");
}
__device__ __forceinline__ void cp_commit() {
    asm volatile("cp.async.commit_group;" ::: "memory");
}
template <int N>
__device__ __forceinline__ void cp_wait() {
    asm volatile("cp.async.wait_group %0;" :: "n"(N) : "memory");
}

// k-permutation within each 16-block: (t, t+4) -> (2t, 2t+1) in each half.
__device__ __forceinline__ int perm16(int t) {
    const int lo = t & 7;
    return (t & 8) + 2 * (lo & 3) + (lo >> 2);
}
__device__ __forceinline__ int permk(int k) {
    return (k & ~15) | perm16(k & 15);
}

// mma.sync m16n8k8 tf32
__device__ __forceinline__ void mma8(float* c, float a0, float a1, float a2,
                                     float a3, float b0, float b1) {
    asm volatile(
        "mma.sync.aligned.m16n8k8.row.col.f32.tf32.tf32.f32 "
        "{%0,%1,%2,%3}, {%4,%5,%6,%7}, {%8,%9}, {%0,%1,%2,%3};"
        : "+f"(c[0]), "+f"(c[1]), "+f"(c[2]), "+f"(c[3])
        : "r"(__float_as_uint(a0)), "r"(__float_as_uint(a1)),
          "r"(__float_as_uint(a2)), "r"(__float_as_uint(a3)),
          "r"(__float_as_uint(b0)), "r"(__float_as_uint(b1)));
}

// ---------------- tiles: 128 rows x 16 k-floats, row stride 20 floats ------
constexpr int LDW    = 20;
constexpr int TILE_F = 128 * LDW;     // 2560 floats
constexpr int TILE_B = TILE_F * 4;    // 10240 bytes

__device__ __forceinline__ void load_tile16(
    uint32_t sbase, const float* __restrict__ g, int ld, int tid)
{
#pragma unroll
    for (int i = 0; i < 2; i++) {
        const int f  = tid + i * 256;     // 0..511 float4s
        const int r  = f >> 2;
        const int c4 = (f & 3) << 2;
        cp16(sbase + (uint32_t)(r * LDW + c4) * 4, g + (size_t)r * ld + c4);
    }
}

// ---------------- main GEMM -------------------------------------------------
// D[m,n] = alpha * sum_k A[m,k]*B[n,k] (+bias[n]) (+resid), 128x128 CTA tile,
// K-chunk 16, 256 threads (occ 2), 2x4 warps, warp tile 64x32 (IT=4).
// EPI: 0=split hi/lo+bias (perm cols; z selects bias/bias2),
// 1=transposed VT+bias (perm seq), 2=alpha scale (perm cols),
// 3=plain tf32 (perm cols), 4=bias+residual.
template <int PASSES, int EPI>
__global__ void __launch_bounds__(256, 2) gemm_mma(
    const float* __restrict__ Ahi, const float* __restrict__ Alo,
    const float* __restrict__ Bhi, const float* __restrict__ Blo,
    float* __restrict__ C, float* __restrict__ C2,
    const float* __restrict__ bias, const float* __restrict__ bias2,
    const float* __restrict__ resid,
    int K, int lda, int ldb, int ldc,
    size_t sA, size_t sB, size_t sC, float alpha)
{
    constexpr int NT = (PASSES == 3) ? 4 : 2;   // tiles per stage
    constexpr int IT = 4;                       // m-subtiles per warp
    extern __shared__ float smf[];
    const uint32_t sb = smem_u32(smf);

    const int tid    = threadIdx.x;
    const int lane   = tid & 31;
    const int wid    = tid >> 5;
    const int warp_m = wid >> 2;      // 0..1
    const int warp_n = wid & 3;       // 0..3
    const int n0 = blockIdx.x * 128;
    const int m0 = blockIdx.y * 128;
    const int z  = blockIdx.z;

    const float* bias_z = (EPI == 0 && z == 1) ? bias2 : bias;

    const float* A0 = Ahi + (size_t)z * sA + (size_t)m0 * lda;
    const float* B0 = Bhi + (size_t)z * sB + (size_t)n0 * ldb;
    const float* A1 = (PASSES == 3) ? Alo + (size_t)z * sA + (size_t)m0 * lda : nullptr;
    const float* B1 = (PASSES == 3) ? Blo + (size_t)z * sB + (size_t)n0 * ldb : nullptr;

    float acc[IT][4][4];
#pragma unroll
    for (int i = 0; i < IT; i++)
#pragma unroll
        for (int j = 0; j < 4; j++)
#pragma unroll
            for (int l = 0; l < 4; l++) acc[i][j][l] = 0.0f;

    const int nch = K / 16;

    auto load_stage = [&](int buf, int c) {
        const uint32_t st = sb + (uint32_t)buf * NT * TILE_B;
        load_tile16(st,          A0 + c * 16, lda, tid);
        load_tile16(st + TILE_B, B0 + c * 16, ldb, tid);
        if (PASSES == 3) {
            load_tile16(st + 2 * TILE_B, A1 + c * 16, lda, tid);
            load_tile16(st + 3 * TILE_B, B1 + c * 16, ldb, tid);
        }
    };

    load_stage(0, 0);
    cp_commit();

    const int arow0 = warp_m * (IT * 16) + (lane >> 2);
    const int bcol0 = warp_n * 32 + (lane >> 2);
    const int kq2   = 2 * (lane & 3);

    for (int c = 0; c < nch; c++) {
        if (c + 1 < nch) {
            load_stage((c + 1) & 1, c + 1);
            cp_commit();
            cp_wait<1>();
        } else {
            cp_wait<0>();
        }
        __syncthreads();

        const float* st  = smf + (size_t)(c & 1) * NT * TILE_F;
        const float* Ath = st;
        const float* Bth = st + TILE_F;
        const float* Atl = st + 2 * TILE_F;
        const float* Btl = st + 3 * TILE_F;

#pragma unroll
        for (int s = 0; s < 2; s++) {
            const int ko = s * 8 + kq2;
            float2 a0[IT], a1[IT], b0[4];
#pragma unroll
            for (int i = 0; i < IT; i++) {
                a0[i] = *reinterpret_cast<const float2*>(
                    Ath + (size_t)(arow0 + i * 16) * LDW + ko);
                a1[i] = *reinterpret_cast<const float2*>(
                    Ath + (size_t)(arow0 + i * 16 + 8) * LDW + ko);
            }
#pragma unroll
            for (int j = 0; j < 4; j++)
                b0[j] = *reinterpret_cast<const float2*>(
                    Bth + (size_t)(bcol0 + j * 8) * LDW + ko);
#pragma unroll
            for (int i = 0; i < IT; i++)
#pragma unroll
                for (int j = 0; j < 4; j++)
                    mma8(acc[i][j], a0[i].x, a1[i].x, a0[i].y, a1[i].y,
                         b0[j].x, b0[j].y);

            if (PASSES == 3) {
                float2 bl[4];
#pragma unroll
                for (int j = 0; j < 4; j++)
                    bl[j] = *reinterpret_cast<const float2*>(
                        Btl + (size_t)(bcol0 + j * 8) * LDW + ko);
#pragma unroll
                for (int i = 0; i < IT; i++)
#pragma unroll
                    for (int j = 0; j < 4; j++)
                        mma8(acc[i][j], a0[i].x, a1[i].x, a0[i].y, a1[i].y,
                             bl[j].x, bl[j].y);
                float2 al0[IT], al1[IT];
#pragma unroll
                for (int i = 0; i < IT; i++) {
                    al0[i] = *reinterpret_cast<const float2*>(
                        Atl + (size_t)(arow0 + i * 16) * LDW + ko);
                    al1[i] = *reinterpret_cast<const float2*>(
                        Atl + (size_t)(arow0 + i * 16 + 8) * LDW + ko);
                }
#pragma unroll
                for (int i = 0; i < IT; i++)
#pragma unroll
                    for (int j = 0; j < 4; j++)
                        mma8(acc[i][j], al0[i].x, al1[i].x, al0[i].y, al1[i].y,
                             b0[j].x, b0[j].y);
            }
        }
        __syncthreads();
    }

    // ---------------- epilogue ----------------
    float* Cz = C + (size_t)z * sC;
#pragma unroll
    for (int i = 0; i < IT; i++) {
#pragma unroll
        for (int j = 0; j < 4; j++) {
            const float* a4 = acc[i][j];
            const int r0 = m0 + warp_m * (IT * 16) + i * 16 + (lane >> 2);
            const int c0 = n0 + warp_n * 32 + j * 8 + 2 * (lane & 3);
            if (EPI == 0) {            // split hi/lo + bias, perm cols
                float* C2z = C2 + (size_t)z * sC;
                const float bx = bias_z[c0], by = bias_z[c0 + 1];
                const int p0 = permk(c0), p1 = permk(c0 + 1);
                const float v0 = a4[0] + bx, v1 = a4[1] + by;
                const float v2 = a4[2] + bx, v3 = a4[3] + by;
                float h;
                h = tf32_rna(v0); Cz[(size_t)r0 * ldc + p0] = h;
                C2z[(size_t)r0 * ldc + p0] = tf32_rna(v0 - h);
                h = tf32_rna(v1); Cz[(size_t)r0 * ldc + p1] = h;
                C2z[(size_t)r0 * ldc + p1] = tf32_rna(v1 - h);
                h = tf32_rna(v2); Cz[(size_t)(r0 + 8) * ldc + p0] = h;
                C2z[(size_t)(r0 + 8) * ldc + p0] = tf32_rna(v2 - h);
                h = tf32_rna(v3); Cz[(size_t)(r0 + 8) * ldc + p1] = h;
                C2z[(size_t)(r0 + 8) * ldc + p1] = tf32_rna(v3 - h);
            } else if (EPI == 1) {     // transposed VT[b][dim][seq], perm seq
                const float bx = bias[c0], by = bias[c0 + 1];
                const int b0i = r0 >> 11,        sx0 = permk(r0 & (SEQ - 1));
                const int b1i = (r0 + 8) >> 11,  sx1 = permk((r0 + 8) & (SEQ - 1));
                float* p0 = C + (size_t)b0i * DIM * SEQ;
                float* p1 = C + (size_t)b1i * DIM * SEQ;
                p0[(size_t)c0 * SEQ + sx0]       = tf32_rna(a4[0] + bx);
                p0[(size_t)(c0 + 1) * SEQ + sx0] = tf32_rna(a4[1] + by);
                p1[(size_t)c0 * SEQ + sx1]       = tf32_rna(a4[2] + bx);
                p1[(size_t)(c0 + 1) * SEQ + sx1] = tf32_rna(a4[3] + by);
            } else if (EPI == 2) {     // alpha scale (scores), perm cols
                const int p0 = permk(c0), p1 = permk(c0 + 1);
                Cz[(size_t)r0 * ldc + p0]       = alpha * a4[0];
                Cz[(size_t)r0 * ldc + p1]       = alpha * a4[1];
                Cz[(size_t)(r0 + 8) * ldc + p0] = alpha * a4[2];
                Cz[(size_t)(r0 + 8) * ldc + p1] = alpha * a4[3];
            } else if (EPI == 3) {     // plain tf32-rounded (O), perm cols
                const int p0 = permk(c0), p1 = permk(c0 + 1);
                Cz[(size_t)r0 * ldc + p0]       = tf32_rna(a4[0]);
                Cz[(size_t)r0 * ldc + p1]       = tf32_rna(a4[1]);
                Cz[(size_t)(r0 + 8) * ldc + p0] = tf32_rna(a4[2]);
                Cz[(size_t)(r0 + 8) * ldc + p1] = tf32_rna(a4[3]);
            } else {                   // bias + residual (final out), no perm
                const float bx = bias[c0], by = bias[c0 + 1];
                const float2 rs0 = *reinterpret_cast<const float2*>(
                    &resid[(size_t)r0 * ldc + c0]);
                const float2 rs1 = *reinterpret_cast<const float2*>(
                    &resid[(size_t)(r0 + 8) * ldc + c0]);
                float2 v0, v1;
                v0.x = a4[0] + bx + rs0.x; v0.y = a4[1] + by + rs0.y;
                v1.x = a4[2] + bx + rs1.x; v1.y = a4[3] + by + rs1.y;
                *reinterpret_cast<float2*>(&Cz[(size_t)r0 * ldc + c0]) = v0;
                *reinterpret_cast<float2*>(&Cz[(size_t)(r0 + 8) * ldc + c0]) = v1;
            }
        }
    }
}

// ---------------- prep: fused splits into combined buffer, perm k ----------
__global__ void split_two(const float4* __restrict__ q, const float4* __restrict__ kv,
                          float* __restrict__ dh, float* __restrict__ dl, int n4)
{
    const int id = blockIdx.x * 256 + threadIdx.x;
    if (id >= 2 * n4) return;
    const float4 v = (id < n4) ? q[id] : kv[id - n4];
    const int e0 = id * 4;
    const int base = e0 & ~511;        // row start (DIM=512 divides rows)
    float vv[4] = {v.x, v.y, v.z, v.w};
#pragma unroll
    for (int u = 0; u < 4; u++) {
        const int k = (e0 + u) & 511;
        const int pk = permk(k);
        const float h = tf32_rna(vv[u]);
        dh[base + pk] = h;
        dl[base + pk] = tf32_rna(vv[u] - h);
    }
}

// ---------------- prep: fused weight transposes, perm k --------------------
__global__ void wprep_all(const float* __restrict__ Wq, const float* __restrict__ Wk,
                          const float* __restrict__ Wv, const float* __restrict__ Wo,
                          float* __restrict__ wqk_hi, float* __restrict__ wqk_lo,
                          float* __restrict__ vh, float* __restrict__ oh)
{
    const int idx = blockIdx.x * 256 + threadIdx.x;  // 0 .. 512*512-1
    const int wsel = blockIdx.y;                     // 0..3
    const int n = idx & 511;        // coalesced read over n
    const int k = idx >> 9;
    const float* W; float *Th, *Tl;
    if      (wsel == 0) { W = Wq; Th = wqk_hi;             Tl = wqk_lo; }
    else if (wsel == 1) { W = Wk; Th = wqk_hi + DIM * DIM; Tl = wqk_lo + DIM * DIM; }
    else if (wsel == 2) { W = Wv; Th = vh; Tl = nullptr; }
    else                { W = Wo; Th = oh; Tl = nullptr; }
    const float w = W[(size_t)k * DIM + n];
    const float h = tf32_rna(w);
    const size_t dst = (size_t)n * DIM + permk(k);
    Th[dst] = h;
    if (Tl) Tl[dst] = tf32_rna(w - h);
}

// ---------------- softmax (rows of 2048), output tf32-rounded --------------
__global__ void __launch_bounds__(256) softmax_rows(float* __restrict__ S)
{
    const size_t row = blockIdx.x;
    float* p = S + row * (size_t)SEQ;
    const int t = threadIdx.x;
    float vals[8];
    float m = -3.402823466e38f;
#pragma unroll
    for (int i = 0; i < 8; i++) { vals[i] = p[t + i * 256]; m = fmaxf(m, vals[i]); }
    __shared__ float red[256];
    red[t] = m; __syncthreads();
#pragma unroll
    for (int s = 128; s > 0; s >>= 1) { if (t < s) red[t] = fmaxf(red[t], red[t+s]); __syncthreads(); }
    m = red[0]; __syncthreads();
    float sum = 0.0f;
#pragma unroll
    for (int i = 0; i < 8; i++) { vals[i] = __expf(vals[i] - m); sum += vals[i]; }
    red[t] = sum; __syncthreads();
#pragma unroll
    for (int s = 128; s > 0; s >>= 1) { if (t < s) red[t] += red[t+s]; __syncthreads(); }
    const float inv = 1.0f / red[0];
#pragma unroll
    for (int i = 0; i < 8; i++) p[t + i * 256] = tf32_rna(vals[i] * inv);
}

// ---------------- launcher --------------------------------------------------
extern "C" void kernel_launch(void* const* d_in, const int* in_sizes, int n_in,
                              void* d_out, int out_size)
{
    (void)in_sizes; (void)n_in; (void)out_size;
    const float* query     = (const float*)d_in[0];
    const float* key_value = (const float*)d_in[1];
    const float* Wq = (const float*)d_in[2];
    const float* bq = (const float*)d_in[3];
    const float* Wk = (const float*)d_in[4];
    const float* bk = (const float*)d_in[5];
    const float* Wv = (const float*)d_in[6];
    const float* bv = (const float*)d_in[7];
    const float* Wo = (const float*)d_in[8];
    const float* bo = (const float*)d_in[9];
    float* out = (float*)d_out;

    float *in_hi, *in_lo, *qk_hi, *qk_lo, *vt, *s, *o;
    float *wqk_hi, *wqk_lo, *wvt, *wot;
    cudaGetSymbolAddress((void**)&in_hi,  g_in_hi);
    cudaGetSymbolAddress((void**)&in_lo,  g_in_lo);
    cudaGetSymbolAddress((void**)&qk_hi,  g_qk_hi);
    cudaGetSymbolAddress((void**)&qk_lo,  g_qk_lo);
    cudaGetSymbolAddress((void**)&vt,     g_vt);
    cudaGetSymbolAddress((void**)&s,      g_s);
    cudaGetSymbolAddress((void**)&o,      g_o);
    cudaGetSymbolAddress((void**)&wqk_hi, g_wqk_hi);
    cudaGetSymbolAddress((void**)&wqk_lo, g_wqk_lo);
    cudaGetSymbolAddress((void**)&wvt,    g_wvt);
    cudaGetSymbolAddress((void**)&wot,    g_wot);

    constexpr int SM3 = 2 * 4 * TILE_B;   // 81920 B (occ 2 -> 160KB/SM)
    constexpr int SM1 = 2 * 2 * TILE_B;   // 40960 B
    cudaFuncSetAttribute(gemm_mma<3,0>, cudaFuncAttributeMaxDynamicSharedMemorySize, SM3);
    cudaFuncSetAttribute(gemm_mma<3,2>, cudaFuncAttributeMaxDynamicSharedMemorySize, SM3);
    cudaFuncSetAttribute(gemm_mma<1,1>, cudaFuncAttributeMaxDynamicSharedMemorySize, SM1);
    cudaFuncSetAttribute(gemm_mma<1,3>, cudaFuncAttributeMaxDynamicSharedMemorySize, SM1);
    cudaFuncSetAttribute(gemm_mma<1,4>, cudaFuncAttributeMaxDynamicSharedMemorySize, SM1);

    const size_t sQKV = (size_t)SEQ * DIM;
    const size_t sS   = (size_t)SEQ * SEQ;
    const size_t sVT  = (size_t)DIM * SEQ;
    const int n4 = (int)(BND / 4);
    const float* q_hi = qk_hi;
    const float* q_lo = qk_lo;
    const float* k_hi = qk_hi + BND;
    const float* k_lo = qk_lo + BND;

    // 0: fused input splits (query + key_value)
    split_two<<<(2 * n4 + 255) / 256, 256>>>((const float4*)query,
        (const float4*)key_value, in_hi, in_lo, n4);
    // 1: fused weight transposes
    {
        dim3 g((DIM * DIM) / 256, 4);
        wprep_all<<<g, 256>>>(Wq, Wk, Wv, Wo, wqk_hi, wqk_lo, wvt, wot);
    }

    // 2: G1+G2 fused: q,k projections (3xTF32, z = projection)
    {
        dim3 grid(DIM / 128, (BB * SEQ) / 128, 2);
        gemm_mma<3,0><<<grid, 256, SM3>>>(in_hi, in_lo, wqk_hi, wqk_lo,
            qk_hi, qk_lo, bq, bk, nullptr, DIM, DIM, DIM, DIM,
            BND, (size_t)DIM * DIM, BND, 1.0f);
    }

    // 3: G4: S = sqrt(512) * q @ k^T (3xTF32, batched)
    {
        dim3 grid(SEQ / 128, SEQ / 128, BB);
        gemm_mma<3,2><<<grid, 256, SM3>>>(q_hi, q_lo, k_hi, k_lo,
            s, nullptr, nullptr, nullptr, nullptr, DIM, DIM, DIM, SEQ,
            sQKV, sQKV, sS, SCALE_F);
    }

    // 4: G3: v projection -> transposed VT (1x)
    {
        dim3 grid(DIM / 128, (BB * SEQ) / 128, 1);
        gemm_mma<1,1><<<grid, 256, SM1>>>(in_hi + BND, nullptr, wvt, nullptr,
            vt, nullptr, bv, nullptr, nullptr, DIM, DIM, DIM, 0, 0, 0, 0, 1.0f);
    }

    // 5: softmax
    softmax_rows<<<BB * SEQ, 256>>>(s);

    // 6: G5: O = P @ V (1x, batched), B = VT
    {
        dim3 grid(DIM / 128, SEQ / 128, BB);
        gemm_mma<1,3><<<grid, 256, SM1>>>(s, nullptr, vt, nullptr,
            o, nullptr, nullptr, nullptr, nullptr, SEQ, SEQ, SEQ, DIM,
            sS, sVT, sQKV, 1.0f);
    }

    // 7: G6: out = query + O @ Wo + bo (1x)
    {
        dim3 grid(DIM / 128, (BB * SEQ) / 128, 1);
        gemm_mma<1,4><<<grid, 256, SM1>>>(o, nullptr, wot, nullptr,
            out, nullptr, bo, nullptr, query, DIM, DIM, DIM, DIM, 0, 0, 0, 1.0f);
    }
}

// round 7
// speedup vs baseline: 1.0291x; 1.0291x over previous
#include <cuda_runtime.h>
#include <cstdint>

// ===========================================================================
// AxisAttention via mma.sync tf32, k-permuted float2-fragment layout.
// 3xTF32 kernels: CTA 128x256, warp tile 64x64, K-chunk 16, 3-stage pipe.
// 1-pass kernels: CTA 128x128, warp tile 64x32, K-chunk 32, occ 2.
// B=4, N=2048, D=DA=512.
// ===========================================================================

constexpr int BB  = 4;
constexpr int SEQ = 2048;
constexpr int DIM = 512;
constexpr float SCALE_F = 22.62741699796952f;  // sqrt(512), multiplied

constexpr size_t BND = (size_t)BB * SEQ * DIM;

// ---------------- device global scratch (no runtime allocation) -----------
__device__ float g_in_hi[2 * BND];     // [query ; key_value] split-hi
__device__ float g_in_lo[2 * BND];
__device__ float g_qk_hi[2 * BND];     // [q ; k] projections split-hi
__device__ float g_qk_lo[2 * BND];
__device__ float g_vt[(size_t)BB * DIM * SEQ];   // V^T per batch [DIM, SEQ]
__device__ float g_s[(size_t)BB * SEQ * SEQ];    // scores / probs
__device__ float g_o[BND];
__device__ float g_wqk_hi[2 * DIM * DIM];        // [Wq^T ; Wk^T]
__device__ float g_wqk_lo[2 * DIM * DIM];
__device__ float g_wvt[DIM * DIM];
__device__ float g_wot[DIM * DIM];

// ---------------- helpers ---------------------------------------------------
__device__ __forceinline__ uint32_t smem_u32(const void* p) {
    uint32_t a;
    asm("{ .reg .u64 t; cvta.to.shared.u64 t, %1; cvt.u32.u64 %0, t; }"
        : "=r"(a) : "l"(p));
    return a;
}
__device__ __forceinline__ float tf32_rna(float x) {
    uint32_t u;
    asm("cvt.rna.tf32.f32 %0, %1;" : "=r"(u) : "f"(x));
    return __uint_as_float(u);
}
__device__ __forceinline__ void cp16(uint32_t saddr, const void* g) {
    asm volatile("cp.async.cg.shared.global [%0], [%1], 16;"
                 :: "r"(saddr), "l"(g) : "memory");
}
__device__ __forceinline__ void cp_commit() {
    asm volatile("cp.async.commit_group;" ::: "memory");
}
template <int N>
__device__ __forceinline__ void cp_wait() {
    asm volatile("cp.async.wait_group %0;" :: "n"(N) : "memory");
}

// k-permutation within each 16-block: (t, t+4) -> (2t, 2t+1) in each half.
__device__ __forceinline__ int perm16(int t) {
    const int lo = t & 7;
    return (t & 8) + 2 * (lo & 3) + (lo >> 2);
}
__device__ __forceinline__ int permk(int k) {
    return (k & ~15) | perm16(k & 15);
}

// mma.sync m16n8k8 tf32
__device__ __forceinline__ void mma8(float* c, float a0, float a1, float a2,
                                     float a3, float b0, float b1) {
    asm volatile(
        "mma.sync.aligned.m16n8k8.row.col.f32.tf32.tf32.f32 "
        "{%0,%1,%2,%3}, {%4,%5,%6,%7}, {%8,%9}, {%0,%1,%2,%3};"
        : "+f"(c[0]), "+f"(c[1]), "+f"(c[2]), "+f"(c[3])
        : "r"(__float_as_uint(a0)), "r"(__float_as_uint(a1)),
          "r"(__float_as_uint(a2)), "r"(__float_as_uint(a3)),
          "r"(__float_as_uint(b0)), "r"(__float_as_uint(b1)));
}

// ---------------- generic async tile loader ---------------------------------
// ROWS x KC floats, row stride LDWp floats. 256 threads.
template <int ROWS, int LDWp>
__device__ __forceinline__ void load_tile(
    uint32_t sbase, const float* __restrict__ g, int ld, int tid)
{
    constexpr int F4R = (LDWp == 20) ? 4 : 8;   // float4s per row (KC/4)
    constexpr int TOT = ROWS * F4R;
#pragma unroll
    for (int i = 0; i < TOT / 256; i++) {
        const int f  = tid + i * 256;
        const int r  = f / F4R;
        const int c4 = (f % F4R) * 4;
        cp16(sbase + (uint32_t)(r * LDWp + c4) * 4, g + (size_t)r * ld + c4);
    }
}

// ---------------- main GEMM -------------------------------------------------
// D[m,n] = alpha * sum_k A[m,k]*B[n,k] (+bias[n]) (+resid).
// PASSES==3: CTA 128x256, warp 64x64 (IT=4, WN=8), KC=16, 3 stages, occ 1.
// PASSES==1: CTA 128x128, warp 64x32 (IT=4, WN=4), KC=32, 2 stages, occ 2.
// EPI: 0=split hi/lo+bias (perm cols; z selects bias/bias2),
// 1=transposed VT+bias (perm seq), 2=alpha scale (perm cols),
// 3=plain tf32 (perm cols), 4=bias+residual.
template <int PASSES, int EPI>
__global__ void __launch_bounds__(256, (PASSES == 3) ? 1 : 2) gemm_mma(
    const float* __restrict__ Ahi, const float* __restrict__ Alo,
    const float* __restrict__ Bhi, const float* __restrict__ Blo,
    float* __restrict__ C, float* __restrict__ C2,
    const float* __restrict__ bias, const float* __restrict__ bias2,
    const float* __restrict__ resid,
    int K, int lda, int ldb, int ldc,
    size_t sA, size_t sB, size_t sC, float alpha)
{
    constexpr int KC     = (PASSES == 3) ? 16 : 32;
    constexpr int LDWp   = (PASSES == 3) ? 20 : 40;
    constexpr int WN     = (PASSES == 3) ? 8 : 4;    // n-subtiles per warp
    constexpr int IT     = 4;                        // m-subtiles per warp
    constexpr int CTAN   = WN * 32;                  // 256 or 128
    constexpr int STAGES = (PASSES == 3) ? 3 : 2;
    constexpr int AT_F   = 128 * LDWp;
    constexpr int BT_F   = CTAN * LDWp;
    constexpr int STAGE_F = (PASSES == 3) ? 2 * (AT_F + BT_F) : (AT_F + BT_F);
    // 3-pass stage layout: [A_hi | A_lo | B_hi | B_lo]
    // 1-pass stage layout: [A_hi | B_hi]
    constexpr int OFF_AL = AT_F;
    constexpr int OFF_BH = (PASSES == 3) ? 2 * AT_F : AT_F;
    constexpr int OFF_BL = 2 * AT_F + BT_F;

    extern __shared__ float smf[];
    const uint32_t sb = smem_u32(smf);

    const int tid    = threadIdx.x;
    const int lane   = tid & 31;
    const int wid    = tid >> 5;
    const int warp_m = wid >> 2;      // 0..1
    const int warp_n = wid & 3;       // 0..3
    const int n0 = blockIdx.x * CTAN;
    const int m0 = blockIdx.y * 128;
    const int z  = blockIdx.z;

    const float* bias_z = (EPI == 0 && z == 1) ? bias2 : bias;

    const float* A0 = Ahi + (size_t)z * sA + (size_t)m0 * lda;
    const float* B0 = Bhi + (size_t)z * sB + (size_t)n0 * ldb;
    const float* A1 = (PASSES == 3) ? Alo + (size_t)z * sA + (size_t)m0 * lda : nullptr;
    const float* B1 = (PASSES == 3) ? Blo + (size_t)z * sB + (size_t)n0 * ldb : nullptr;

    float acc[IT][WN][4];
#pragma unroll
    for (int i = 0; i < IT; i++)
#pragma unroll
        for (int j = 0; j < WN; j++)
#pragma unroll
            for (int l = 0; l < 4; l++) acc[i][j][l] = 0.0f;

    const int nch = K / KC;

    auto load_stage = [&](int buf, int c) {
        const uint32_t st = sb + (uint32_t)buf * STAGE_F * 4;
        load_tile<128, LDWp>(st, A0 + c * KC, lda, tid);
        load_tile<CTAN, LDWp>(st + OFF_BH * 4, B0 + c * KC, ldb, tid);
        if (PASSES == 3) {
            load_tile<128, LDWp>(st + OFF_AL * 4, A1 + c * KC, lda, tid);
            load_tile<CTAN, LDWp>(st + OFF_BL * 4, B1 + c * KC, ldb, tid);
        }
    };

    // prologue: prefetch stages 0..STAGES-2
#pragma unroll
    for (int s = 0; s < STAGES - 1; s++) {
        load_stage(s, s);
        cp_commit();
    }

    const int arow0 = warp_m * 64 + (lane >> 2);
    const int bcol0 = warp_n * (WN * 8) + (lane >> 2);
    const int kq2   = 2 * (lane & 3);

    for (int c = 0; c < nch; c++) {
        if (c + STAGES - 1 < nch) load_stage((c + STAGES - 1) % STAGES, c + STAGES - 1);
        cp_commit();
        cp_wait<STAGES - 1>();
        __syncthreads();

        const float* st  = smf + (size_t)(c % STAGES) * STAGE_F;
        const float* Ath = st;
        const float* Bth = st + OFF_BH;
        const float* Atl = st + OFF_AL;
        const float* Btl = st + OFF_BL;

#pragma unroll
        for (int s = 0; s < KC / 8; s++) {
            const int ko = s * 8 + kq2;
            float2 a0[IT], a1[IT], b0[WN];
#pragma unroll
            for (int i = 0; i < IT; i++) {
                a0[i] = *reinterpret_cast<const float2*>(
                    Ath + (size_t)(arow0 + i * 16) * LDWp + ko);
                a1[i] = *reinterpret_cast<const float2*>(
                    Ath + (size_t)(arow0 + i * 16 + 8) * LDWp + ko);
            }
#pragma unroll
            for (int j = 0; j < WN; j++)
                b0[j] = *reinterpret_cast<const float2*>(
                    Bth + (size_t)(bcol0 + j * 8) * LDWp + ko);
#pragma unroll
            for (int i = 0; i < IT; i++)
#pragma unroll
                for (int j = 0; j < WN; j++)
                    mma8(acc[i][j], a0[i].x, a1[i].x, a0[i].y, a1[i].y,
                         b0[j].x, b0[j].y);

            if (PASSES == 3) {
                float2 bl[WN];
#pragma unroll
                for (int j = 0; j < WN; j++)
                    bl[j] = *reinterpret_cast<const float2*>(
                        Btl + (size_t)(bcol0 + j * 8) * LDWp + ko);
#pragma unroll
                for (int i = 0; i < IT; i++)
#pragma unroll
                    for (int j = 0; j < WN; j++)
                        mma8(acc[i][j], a0[i].x, a1[i].x, a0[i].y, a1[i].y,
                             bl[j].x, bl[j].y);
                float2 al0[IT], al1[IT];
#pragma unroll
                for (int i = 0; i < IT; i++) {
                    al0[i] = *reinterpret_cast<const float2*>(
                        Atl + (size_t)(arow0 + i * 16) * LDWp + ko);
                    al1[i] = *reinterpret_cast<const float2*>(
                        Atl + (size_t)(arow0 + i * 16 + 8) * LDWp + ko);
                }
#pragma unroll
                for (int i = 0; i < IT; i++)
#pragma unroll
                    for (int j = 0; j < WN; j++)
                        mma8(acc[i][j], al0[i].x, al1[i].x, al0[i].y, al1[i].y,
                             b0[j].x, b0[j].y);
            }
        }
        __syncthreads();
    }

    // ---------------- epilogue ----------------
    float* Cz = C + (size_t)z * sC;
#pragma unroll
    for (int i = 0; i < IT; i++) {
#pragma unroll
        for (int j = 0; j < WN; j++) {
            const float* a4 = acc[i][j];
            const int r0 = m0 + warp_m * 64 + i * 16 + (lane >> 2);
            const int c0 = n0 + warp_n * (WN * 8) + j * 8 + 2 * (lane & 3);
            if (EPI == 0) {            // split hi/lo + bias, perm cols
                float* C2z = C2 + (size_t)z * sC;
                const float bx = bias_z[c0], by = bias_z[c0 + 1];
                const int p0 = permk(c0), p1 = permk(c0 + 1);
                const float v0 = a4[0] + bx, v1 = a4[1] + by;
                const float v2 = a4[2] + bx, v3 = a4[3] + by;
                float h;
                h = tf32_rna(v0); Cz[(size_t)r0 * ldc + p0] = h;
                C2z[(size_t)r0 * ldc + p0] = tf32_rna(v0 - h);
                h = tf32_rna(v1); Cz[(size_t)r0 * ldc + p1] = h;
                C2z[(size_t)r0 * ldc + p1] = tf32_rna(v1 - h);
                h = tf32_rna(v2); Cz[(size_t)(r0 + 8) * ldc + p0] = h;
                C2z[(size_t)(r0 + 8) * ldc + p0] = tf32_rna(v2 - h);
                h = tf32_rna(v3); Cz[(size_t)(r0 + 8) * ldc + p1] = h;
                C2z[(size_t)(r0 + 8) * ldc + p1] = tf32_rna(v3 - h);
            } else if (EPI == 1) {     // transposed VT[b][dim][seq], perm seq
                const float bx = bias[c0], by = bias[c0 + 1];
                const int b0i = r0 >> 11,        sx0 = permk(r0 & (SEQ - 1));
                const int b1i = (r0 + 8) >> 11,  sx1 = permk((r0 + 8) & (SEQ - 1));
                float* p0 = C + (size_t)b0i * DIM * SEQ;
                float* p1 = C + (size_t)b1i * DIM * SEQ;
                p0[(size_t)c0 * SEQ + sx0]       = tf32_rna(a4[0] + bx);
                p0[(size_t)(c0 + 1) * SEQ + sx0] = tf32_rna(a4[1] + by);
                p1[(size_t)c0 * SEQ + sx1]       = tf32_rna(a4[2] + bx);
                p1[(size_t)(c0 + 1) * SEQ + sx1] = tf32_rna(a4[3] + by);
            } else if (EPI == 2) {     // alpha scale (scores), perm cols
                const int p0 = permk(c0), p1 = permk(c0 + 1);
                Cz[(size_t)r0 * ldc + p0]       = alpha * a4[0];
                Cz[(size_t)r0 * ldc + p1]       = alpha * a4[1];
                Cz[(size_t)(r0 + 8) * ldc + p0] = alpha * a4[2];
                Cz[(size_t)(r0 + 8) * ldc + p1] = alpha * a4[3];
            } else if (EPI == 3) {     // plain tf32-rounded (O), perm cols
                const int p0 = permk(c0), p1 = permk(c0 + 1);
                Cz[(size_t)r0 * ldc + p0]       = tf32_rna(a4[0]);
                Cz[(size_t)r0 * ldc + p1]       = tf32_rna(a4[1]);
                Cz[(size_t)(r0 + 8) * ldc + p0] = tf32_rna(a4[2]);
                Cz[(size_t)(r0 + 8) * ldc + p1] = tf32_rna(a4[3]);
            } else {                   // bias + residual (final out), no perm
                const float bx = bias[c0], by = bias[c0 + 1];
                const float2 rs0 = *reinterpret_cast<const float2*>(
                    &resid[(size_t)r0 * ldc + c0]);
                const float2 rs1 = *reinterpret_cast<const float2*>(
                    &resid[(size_t)(r0 + 8) * ldc + c0]);
                float2 v0, v1;
                v0.x = a4[0] + bx + rs0.x; v0.y = a4[1] + by + rs0.y;
                v1.x = a4[2] + bx + rs1.x; v1.y = a4[3] + by + rs1.y;
                *reinterpret_cast<float2*>(&Cz[(size_t)r0 * ldc + c0]) = v0;
                *reinterpret_cast<float2*>(&Cz[(size_t)(r0 + 8) * ldc + c0]) = v1;
            }
        }
    }
}

// ---------------- prep: fused splits into combined buffer, perm k ----------
__global__ void split_two(const float4* __restrict__ q, const float4* __restrict__ kv,
                          float* __restrict__ dh, float* __restrict__ dl, int n4)
{
    const int id = blockIdx.x * 256 + threadIdx.x;
    if (id >= 2 * n4) return;
    const float4 v = (id < n4) ? q[id] : kv[id - n4];
    const int e0 = id * 4;
    const int base = e0 & ~511;        // row start (DIM=512 divides rows)
    float vv[4] = {v.x, v.y, v.z, v.w};
#pragma unroll
    for (int u = 0; u < 4; u++) {
        const int k = (e0 + u) & 511;
        const int pk = permk(k);
        const float h = tf32_rna(vv[u]);
        dh[base + pk] = h;
        dl[base + pk] = tf32_rna(vv[u] - h);
    }
}

// ---------------- prep: fused weight transposes, perm k --------------------
__global__ void wprep_all(const float* __restrict__ Wq, const float* __restrict__ Wk,
                          const float* __restrict__ Wv, const float* __restrict__ Wo,
                          float* __restrict__ wqk_hi, float* __restrict__ wqk_lo,
                          float* __restrict__ vh, float* __restrict__ oh)
{
    const int idx = blockIdx.x * 256 + threadIdx.x;  // 0 .. 512*512-1
    const int wsel = blockIdx.y;                     // 0..3
    const int n = idx & 511;        // coalesced read over n
    const int k = idx >> 9;
    const float* W; float *Th, *Tl;
    if      (wsel == 0) { W = Wq; Th = wqk_hi;             Tl = wqk_lo; }
    else if (wsel == 1) { W = Wk; Th = wqk_hi + DIM * DIM; Tl = wqk_lo + DIM * DIM; }
    else if (wsel == 2) { W = Wv; Th = vh; Tl = nullptr; }
    else                { W = Wo; Th = oh; Tl = nullptr; }
    const float w = W[(size_t)k * DIM + n];
    const float h = tf32_rna(w);
    const size_t dst = (size_t)n * DIM + permk(k);
    Th[dst] = h;
    if (Tl) Tl[dst] = tf32_rna(w - h);
}

// ---------------- softmax (rows of 2048), output tf32-rounded --------------
__global__ void __launch_bounds__(256) softmax_rows(float* __restrict__ S)
{
    const size_t row = blockIdx.x;
    float* p = S + row * (size_t)SEQ;
    const int t = threadIdx.x;
    float vals[8];
    float m = -3.402823466e38f;
#pragma unroll
    for (int i = 0; i < 8; i++) { vals[i] = p[t + i * 256]; m = fmaxf(m, vals[i]); }
    __shared__ float red[256];
    red[t] = m; __syncthreads();
#pragma unroll
    for (int s = 128; s > 0; s >>= 1) { if (t < s) red[t] = fmaxf(red[t], red[t+s]); __syncthreads(); }
    m = red[0]; __syncthreads();
    float sum = 0.0f;
#pragma unroll
    for (int i = 0; i < 8; i++) { vals[i] = __expf(vals[i] - m); sum += vals[i]; }
    red[t] = sum; __syncthreads();
#pragma unroll
    for (int s = 128; s > 0; s >>= 1) { if (t < s) red[t] += red[t+s]; __syncthreads(); }
    const float inv = 1.0f / red[0];
#pragma unroll
    for (int i = 0; i < 8; i++) p[t + i * 256] = tf32_rna(vals[i] * inv);
}

// ---------------- launcher --------------------------------------------------
extern "C" void kernel_launch(void* const* d_in, const int* in_sizes, int n_in,
                              void* d_out, int out_size)
{
    (void)in_sizes; (void)n_in; (void)out_size;
    const float* query     = (const float*)d_in[0];
    const float* key_value = (const float*)d_in[1];
    const float* Wq = (const float*)d_in[2];
    const float* bq = (const float*)d_in[3];
    const float* Wk = (const float*)d_in[4];
    const float* bk = (const float*)d_in[5];
    const float* Wv = (const float*)d_in[6];
    const float* bv = (const float*)d_in[7];
    const float* Wo = (const float*)d_in[8];
    const float* bo = (const float*)d_in[9];
    float* out = (float*)d_out;

    float *in_hi, *in_lo, *qk_hi, *qk_lo, *vt, *s, *o;
    float *wqk_hi, *wqk_lo, *wvt, *wot;
    cudaGetSymbolAddress((void**)&in_hi,  g_in_hi);
    cudaGetSymbolAddress((void**)&in_lo,  g_in_lo);
    cudaGetSymbolAddress((void**)&qk_hi,  g_qk_hi);
    cudaGetSymbolAddress((void**)&qk_lo,  g_qk_lo);
    cudaGetSymbolAddress((void**)&vt,     g_vt);
    cudaGetSymbolAddress((void**)&s,      g_s);
    cudaGetSymbolAddress((void**)&o,      g_o);
    cudaGetSymbolAddress((void**)&wqk_hi, g_wqk_hi);
    cudaGetSymbolAddress((void**)&wqk_lo, g_wqk_lo);
    cudaGetSymbolAddress((void**)&wvt,    g_wvt);
    cudaGetSymbolAddress((void**)&wot,    g_wot);

    // 3-pass: 3 stages x (128+256)*20 floats * 2(hi/lo) = 184320 B
    constexpr int SM3 = 3 * 2 * (128 + 256) * 20 * 4;
    // 1-pass: 2 stages x (128+128)*40 floats = 81920 B
    constexpr int SM1 = 2 * (128 + 128) * 40 * 4;
    cudaFuncSetAttribute(gemm_mma<3,0>, cudaFuncAttributeMaxDynamicSharedMemorySize, SM3);
    cudaFuncSetAttribute(gemm_mma<3,2>, cudaFuncAttributeMaxDynamicSharedMemorySize, SM3);
    cudaFuncSetAttribute(gemm_mma<1,1>, cudaFuncAttributeMaxDynamicSharedMemorySize, SM1);
    cudaFuncSetAttribute(gemm_mma<1,3>, cudaFuncAttributeMaxDynamicSharedMemorySize, SM1);
    cudaFuncSetAttribute(gemm_mma<1,4>, cudaFuncAttributeMaxDynamicSharedMemorySize, SM1);

    const size_t sQKV = (size_t)SEQ * DIM;
    const size_t sS   = (size_t)SEQ * SEQ;
    const size_t sVT  = (size_t)DIM * SEQ;
    const int n4 = (int)(BND / 4);
    const float* q_hi = qk_hi;
    const float* q_lo = qk_lo;
    const float* k_hi = qk_hi + BND;
    const float* k_lo = qk_lo + BND;

    // 0: fused input splits (query + key_value)
    split_two<<<(2 * n4 + 255) / 256, 256>>>((const float4*)query,
        (const float4*)key_value, in_hi, in_lo, n4);
    // 1: fused weight transposes
    {
        dim3 g((DIM * DIM) / 256, 4);
        wprep_all<<<g, 256>>>(Wq, Wk, Wv, Wo, wqk_hi, wqk_lo, wvt, wot);
    }

    // 2: G1+G2 fused: q,k projections (3xTF32, CTA 128x256, z = projection)
    {
        dim3 grid(DIM / 256, (BB * SEQ) / 128, 2);
        gemm_mma<3,0><<<grid, 256, SM3>>>(in_hi, in_lo, wqk_hi, wqk_lo,
            qk_hi, qk_lo, bq, bk, nullptr, DIM, DIM, DIM, DIM,
            BND, (size_t)DIM * DIM, BND, 1.0f);
    }

    // 3: G4: S = sqrt(512) * q @ k^T (3xTF32, CTA 128x256, batched)
    {
        dim3 grid(SEQ / 256, SEQ / 128, BB);
        gemm_mma<3,2><<<grid, 256, SM3>>>(q_hi, q_lo, k_hi, k_lo,
            s, nullptr, nullptr, nullptr, nullptr, DIM, DIM, DIM, SEQ,
            sQKV, sQKV, sS, SCALE_F);
    }

    // 4: G3: v projection -> transposed VT (1x)
    {
        dim3 grid(DIM / 128, (BB * SEQ) / 128, 1);
        gemm_mma<1,1><<<grid, 256, SM1>>>(in_hi + BND, nullptr, wvt, nullptr,
            vt, nullptr, bv, nullptr, nullptr, DIM, DIM, DIM, 0, 0, 0, 0, 1.0f);
    }

    // 5: softmax
    softmax_rows<<<BB * SEQ, 256>>>(s);

    // 6: G5: O = P @ V (1x, batched), B = VT
    {
        dim3 grid(DIM / 128, SEQ / 128, BB);
        gemm_mma<1,3><<<grid, 256, SM1>>>(s, nullptr, vt, nullptr,
            o, nullptr, nullptr, nullptr, nullptr, SEQ, SEQ, SEQ, DIM,
            sS, sVT, sQKV, 1.0f);
    }

    // 7: G6: out = query + O @ Wo + bo (1x)
    {
        dim3 grid(DIM / 128, (BB * SEQ) / 128, 1);
        gemm_mma<1,4><<<grid, 256, SM1>>>(o, nullptr, wot, nullptr,
            out, nullptr, bo, nullptr, query, DIM, DIM, DIM, DIM, 0, 0, 0, 1.0f);
    }
}

// round 8
// speedup vs baseline: 1.1536x; 1.1210x over previous
#include <cuda_runtime.h>
#include <cstdint>

// ===========================================================================
// AxisAttention via mma.sync tf32, k-permuted float2-fragment layout.
// 3xTF32 (512 thr, IT=2, K32) with software-pipelined fragment loads for
// q/k projections and QK^T; single-pass tf32 (256 thr, occ 2) for v-proj,
// PV, out-proj. B=4, N=2048, D=DA=512.
// ===========================================================================

constexpr int BB  = 4;
constexpr int SEQ = 2048;
constexpr int DIM = 512;
constexpr float SCALE_F = 22.62741699796952f;  // sqrt(512), multiplied

constexpr size_t BND = (size_t)BB * SEQ * DIM;

// ---------------- device global scratch (no runtime allocation) -----------
__device__ float g_in_hi[2 * BND];     // [query ; key_value] split-hi
__device__ float g_in_lo[2 * BND];
__device__ float g_qk_hi[2 * BND];     // [q ; k] projections split-hi
__device__ float g_qk_lo[2 * BND];
__device__ float g_vt[(size_t)BB * DIM * SEQ];   // V^T per batch [DIM, SEQ]
__device__ float g_s[(size_t)BB * SEQ * SEQ];    // scores / probs
__device__ float g_o[BND];
__device__ float g_wqk_hi[2 * DIM * DIM];        // [Wq^T ; Wk^T]
__device__ float g_wqk_lo[2 * DIM * DIM];
__device__ float g_wvt[DIM * DIM];
__device__ float g_wot[DIM * DIM];

// ---------------- helpers ---------------------------------------------------
__device__ __forceinline__ uint32_t smem_u32(const void* p) {
    uint32_t a;
    asm("{ .reg .u64 t; cvta.to.shared.u64 t, %1; cvt.u32.u64 %0, t; }"
        : "=r"(a) : "l"(p));
    return a;
}
__device__ __forceinline__ float tf32_rna(float x) {
    uint32_t u;
    asm("cvt.rna.tf32.f32 %0, %1;" : "=r"(u) : "f"(x));
    return __uint_as_float(u);
}
__device__ __forceinline__ void cp16(uint32_t saddr, const void* g) {
    asm volatile("cp.async.cg.shared.global [%0], [%1], 16;"
                 :: "r"(saddr), "l"(g) : "memory");
}
__device__ __forceinline__ void cp_commit() {
    asm volatile("cp.async.commit_group;" ::: "memory");
}
template <int N>
__device__ __forceinline__ void cp_wait() {
    asm volatile("cp.async.wait_group %0;" :: "n"(N) : "memory");
}

// k-permutation within each 16-block: (t, t+4) -> (2t, 2t+1) in each half.
__device__ __forceinline__ int perm16(int t) {
    const int lo = t & 7;
    return (t & 8) + 2 * (lo & 3) + (lo >> 2);
}
__device__ __forceinline__ int permk(int k) {
    return (k & ~15) | perm16(k & 15);
}

// mma.sync m16n8k8 tf32
__device__ __forceinline__ void mma8(float* c, float a0, float a1, float a2,
                                     float a3, float b0, float b1) {
    asm volatile(
        "mma.sync.aligned.m16n8k8.row.col.f32.tf32.tf32.f32 "
        "{%0,%1,%2,%3}, {%4,%5,%6,%7}, {%8,%9}, {%0,%1,%2,%3};"
        : "+f"(c[0]), "+f"(c[1]), "+f"(c[2]), "+f"(c[3])
        : "r"(__float_as_uint(a0)), "r"(__float_as_uint(a1)),
          "r"(__float_as_uint(a2)), "r"(__float_as_uint(a3)),
          "r"(__float_as_uint(b0)), "r"(__float_as_uint(b1)));
}

// ---------------- tiles: 128 rows x 32 k-floats, row stride 40 floats ------
constexpr int LDW    = 40;
constexpr int TILE_F = 128 * LDW;     // 5120 floats
constexpr int TILE_B = TILE_F * 4;    // 20480 bytes

template <int THREADS>
__device__ __forceinline__ void load_tile32(
    uint32_t sbase, const float* __restrict__ g, int ld, int tid)
{
#pragma unroll
    for (int i = 0; i < 1024 / THREADS; i++) {
        const int f  = tid + i * THREADS;  // 0..1023 float4s
        const int r  = f >> 3;
        const int c4 = (f & 7) << 2;
        cp16(sbase + (uint32_t)(r * LDW + c4) * 4, g + (size_t)r * ld + c4);
    }
}

// ---------------- main GEMM -------------------------------------------------
// D[m,n] = alpha * sum_k A[m,k]*B[n,k] (+bias[n]) (+resid), 128x128 CTA tile,
// K-chunk 32. PASSES==3: 512 threads, 4x4 warps, warp tile 32x32,
// software-pipelined fragment loads (double-buffered registers).
// PASSES==1: 256 threads (occ 2), 2x4 warps, warp tile 64x32.
// EPI: 0=split hi/lo+bias (perm cols; z selects bias/bias2),
// 1=transposed VT+bias (perm seq), 2=alpha scale (perm cols),
// 3=plain tf32 (perm cols), 4=bias+residual.
template <int PASSES, int EPI>
__global__ void __launch_bounds__((PASSES == 3) ? 512 : 256,
                                  (PASSES == 3) ? 1 : 2) gemm_mma(
    const float* __restrict__ Ahi, const float* __restrict__ Alo,
    const float* __restrict__ Bhi, const float* __restrict__ Blo,
    float* __restrict__ C, float* __restrict__ C2,
    const float* __restrict__ bias, const float* __restrict__ bias2,
    const float* __restrict__ resid,
    int K, int lda, int ldb, int ldc,
    size_t sA, size_t sB, size_t sC, float alpha)
{
    constexpr int NT      = (PASSES == 3) ? 4 : 2;   // tiles per stage
    constexpr int THREADS = (PASSES == 3) ? 512 : 256;
    constexpr int IT      = (PASSES == 3) ? 2 : 4;   // m-subtiles per warp
    extern __shared__ float smf[];
    const uint32_t sb = smem_u32(smf);

    const int tid    = threadIdx.x;
    const int lane   = tid & 31;
    const int wid    = tid >> 5;
    const int warp_m = wid >> 2;
    const int warp_n = wid & 3;
    const int n0 = blockIdx.x * 128;
    const int m0 = blockIdx.y * 128;
    const int z  = blockIdx.z;

    const float* bias_z = (EPI == 0 && z == 1) ? bias2 : bias;

    const float* A0 = Ahi + (size_t)z * sA + (size_t)m0 * lda;
    const float* B0 = Bhi + (size_t)z * sB + (size_t)n0 * ldb;
    const float* A1 = (PASSES == 3) ? Alo + (size_t)z * sA + (size_t)m0 * lda : nullptr;
    const float* B1 = (PASSES == 3) ? Blo + (size_t)z * sB + (size_t)n0 * ldb : nullptr;

    float acc[IT][4][4];
#pragma unroll
    for (int i = 0; i < IT; i++)
#pragma unroll
        for (int j = 0; j < 4; j++)
#pragma unroll
            for (int l = 0; l < 4; l++) acc[i][j][l] = 0.0f;

    const int nch = K / 32;

    auto load_stage = [&](int buf, int c) {
        const uint32_t st = sb + (uint32_t)buf * NT * TILE_B;
        load_tile32<THREADS>(st,          A0 + c * 32, lda, tid);
        load_tile32<THREADS>(st + TILE_B, B0 + c * 32, ldb, tid);
        if (PASSES == 3) {
            load_tile32<THREADS>(st + 2 * TILE_B, A1 + c * 32, lda, tid);
            load_tile32<THREADS>(st + 3 * TILE_B, B1 + c * 32, ldb, tid);
        }
    };

    load_stage(0, 0);
    cp_commit();

    const int arow0 = warp_m * (IT * 16) + (lane >> 2);
    const int bcol0 = warp_n * 32 + (lane >> 2);
    const int kq2   = 2 * (lane & 3);

    for (int c = 0; c < nch; c++) {
        if (c + 1 < nch) {
            load_stage((c + 1) & 1, c + 1);
            cp_commit();
            cp_wait<1>();
        } else {
            cp_wait<0>();
        }
        __syncthreads();

        const float* st  = smf + (size_t)(c & 1) * NT * TILE_F;
        const float* Ath = st;
        const float* Bth = st + TILE_F;
        const float* Atl = st + 2 * TILE_F;
        const float* Btl = st + 3 * TILE_F;

        if (PASSES == 3) {
            // --------- software-pipelined fragment loads (double buffer) ----
            float2 a0[2][IT], a1[2][IT], b0[2][4];
            float2 al0[2][IT], al1[2][IT], bl[2][4];

            auto load_frags = [&](int buf, int s) {
                const int ko = s * 8 + kq2;
#pragma unroll
                for (int i = 0; i < IT; i++) {
                    a0[buf][i] = *reinterpret_cast<const float2*>(
                        Ath + (size_t)(arow0 + i * 16) * LDW + ko);
                    a1[buf][i] = *reinterpret_cast<const float2*>(
                        Ath + (size_t)(arow0 + i * 16 + 8) * LDW + ko);
                    al0[buf][i] = *reinterpret_cast<const float2*>(
                        Atl + (size_t)(arow0 + i * 16) * LDW + ko);
                    al1[buf][i] = *reinterpret_cast<const float2*>(
                        Atl + (size_t)(arow0 + i * 16 + 8) * LDW + ko);
                }
#pragma unroll
                for (int j = 0; j < 4; j++) {
                    b0[buf][j] = *reinterpret_cast<const float2*>(
                        Bth + (size_t)(bcol0 + j * 8) * LDW + ko);
                    bl[buf][j] = *reinterpret_cast<const float2*>(
                        Btl + (size_t)(bcol0 + j * 8) * LDW + ko);
                }
            };

            load_frags(0, 0);
#pragma unroll
            for (int s = 0; s < 4; s++) {
                const int cur = s & 1;
                if (s < 3) load_frags(cur ^ 1, s + 1);
#pragma unroll
                for (int i = 0; i < IT; i++)
#pragma unroll
                    for (int j = 0; j < 4; j++)
                        mma8(acc[i][j], a0[cur][i].x, a1[cur][i].x,
                             a0[cur][i].y, a1[cur][i].y,
                             b0[cur][j].x, b0[cur][j].y);
#pragma unroll
                for (int i = 0; i < IT; i++)
#pragma unroll
                    for (int j = 0; j < 4; j++)
                        mma8(acc[i][j], a0[cur][i].x, a1[cur][i].x,
                             a0[cur][i].y, a1[cur][i].y,
                             bl[cur][j].x, bl[cur][j].y);
#pragma unroll
                for (int i = 0; i < IT; i++)
#pragma unroll
                    for (int j = 0; j < 4; j++)
                        mma8(acc[i][j], al0[cur][i].x, al1[cur][i].x,
                             al0[cur][i].y, al1[cur][i].y,
                             b0[cur][j].x, b0[cur][j].y);
            }
        } else {
            // --------- single-pass mainloop (unchanged) ---------------------
#pragma unroll
            for (int s = 0; s < 4; s++) {
                const int ko = s * 8 + kq2;
                float2 a0[IT], a1[IT], b0[4];
#pragma unroll
                for (int i = 0; i < IT; i++) {
                    a0[i] = *reinterpret_cast<const float2*>(
                        Ath + (size_t)(arow0 + i * 16) * LDW + ko);
                    a1[i] = *reinterpret_cast<const float2*>(
                        Ath + (size_t)(arow0 + i * 16 + 8) * LDW + ko);
                }
#pragma unroll
                for (int j = 0; j < 4; j++)
                    b0[j] = *reinterpret_cast<const float2*>(
                        Bth + (size_t)(bcol0 + j * 8) * LDW + ko);
#pragma unroll
                for (int i = 0; i < IT; i++)
#pragma unroll
                    for (int j = 0; j < 4; j++)
                        mma8(acc[i][j], a0[i].x, a1[i].x, a0[i].y, a1[i].y,
                             b0[j].x, b0[j].y);
            }
        }
        __syncthreads();
    }

    // ---------------- epilogue ----------------
    float* Cz = C + (size_t)z * sC;
#pragma unroll
    for (int i = 0; i < IT; i++) {
#pragma unroll
        for (int j = 0; j < 4; j++) {
            const float* a4 = acc[i][j];
            const int r0 = m0 + warp_m * (IT * 16) + i * 16 + (lane >> 2);
            const int c0 = n0 + warp_n * 32 + j * 8 + 2 * (lane & 3);
            if (EPI == 0) {            // split hi/lo + bias, perm cols
                float* C2z = C2 + (size_t)z * sC;
                const float bx = bias_z[c0], by = bias_z[c0 + 1];
                const int p0 = permk(c0), p1 = permk(c0 + 1);
                const float v0 = a4[0] + bx, v1 = a4[1] + by;
                const float v2 = a4[2] + bx, v3 = a4[3] + by;
                float h;
                h = tf32_rna(v0); Cz[(size_t)r0 * ldc + p0] = h;
                C2z[(size_t)r0 * ldc + p0] = tf32_rna(v0 - h);
                h = tf32_rna(v1); Cz[(size_t)r0 * ldc + p1] = h;
                C2z[(size_t)r0 * ldc + p1] = tf32_rna(v1 - h);
                h = tf32_rna(v2); Cz[(size_t)(r0 + 8) * ldc + p0] = h;
                C2z[(size_t)(r0 + 8) * ldc + p0] = tf32_rna(v2 - h);
                h = tf32_rna(v3); Cz[(size_t)(r0 + 8) * ldc + p1] = h;
                C2z[(size_t)(r0 + 8) * ldc + p1] = tf32_rna(v3 - h);
            } else if (EPI == 1) {     // transposed VT[b][dim][seq], perm seq
                const float bx = bias[c0], by = bias[c0 + 1];
                const int b0i = r0 >> 11,        sx0 = permk(r0 & (SEQ - 1));
                const int b1i = (r0 + 8) >> 11,  sx1 = permk((r0 + 8) & (SEQ - 1));
                float* p0 = C + (size_t)b0i * DIM * SEQ;
                float* p1 = C + (size_t)b1i * DIM * SEQ;
                p0[(size_t)c0 * SEQ + sx0]       = tf32_rna(a4[0] + bx);
                p0[(size_t)(c0 + 1) * SEQ + sx0] = tf32_rna(a4[1] + by);
                p1[(size_t)c0 * SEQ + sx1]       = tf32_rna(a4[2] + bx);
                p1[(size_t)(c0 + 1) * SEQ + sx1] = tf32_rna(a4[3] + by);
            } else if (EPI == 2) {     // alpha scale (scores), perm cols
                const int p0 = permk(c0), p1 = permk(c0 + 1);
                Cz[(size_t)r0 * ldc + p0]       = alpha * a4[0];
                Cz[(size_t)r0 * ldc + p1]       = alpha * a4[1];
                Cz[(size_t)(r0 + 8) * ldc + p0] = alpha * a4[2];
                Cz[(size_t)(r0 + 8) * ldc + p1] = alpha * a4[3];
            } else if (EPI == 3) {     // plain tf32-rounded (O), perm cols
                const int p0 = permk(c0), p1 = permk(c0 + 1);
                Cz[(size_t)r0 * ldc + p0]       = tf32_rna(a4[0]);
                Cz[(size_t)r0 * ldc + p1]       = tf32_rna(a4[1]);
                Cz[(size_t)(r0 + 8) * ldc + p0] = tf32_rna(a4[2]);
                Cz[(size_t)(r0 + 8) * ldc + p1] = tf32_rna(a4[3]);
            } else {                   // bias + residual (final out), no perm
                const float bx = bias[c0], by = bias[c0 + 1];
                const float2 rs0 = *reinterpret_cast<const float2*>(
                    &resid[(size_t)r0 * ldc + c0]);
                const float2 rs1 = *reinterpret_cast<const float2*>(
                    &resid[(size_t)(r0 + 8) * ldc + c0]);
                float2 v0, v1;
                v0.x = a4[0] + bx + rs0.x; v0.y = a4[1] + by + rs0.y;
                v1.x = a4[2] + bx + rs1.x; v1.y = a4[3] + by + rs1.y;
                *reinterpret_cast<float2*>(&Cz[(size_t)r0 * ldc + c0]) = v0;
                *reinterpret_cast<float2*>(&Cz[(size_t)(r0 + 8) * ldc + c0]) = v1;
            }
        }
    }
}

// ---------------- prep: fused splits into combined buffer, perm k ----------
__global__ void split_two(const float4* __restrict__ q, const float4* __restrict__ kv,
                          float* __restrict__ dh, float* __restrict__ dl, int n4)
{
    const int id = blockIdx.x * 256 + threadIdx.x;
    if (id >= 2 * n4) return;
    const float4 v = (id < n4) ? q[id] : kv[id - n4];
    const int e0 = id * 4;
    const int base = e0 & ~511;        // row start (DIM=512 divides rows)
    float vv[4] = {v.x, v.y, v.z, v.w};
#pragma unroll
    for (int u = 0; u < 4; u++) {
        const int k = (e0 + u) & 511;
        const int pk = permk(k);
        const float h = tf32_rna(vv[u]);
        dh[base + pk] = h;
        dl[base + pk] = tf32_rna(vv[u] - h);
    }
}

// ---------------- prep: fused weight transposes, perm k --------------------
__global__ void wprep_all(const float* __restrict__ Wq, const float* __restrict__ Wk,
                          const float* __restrict__ Wv, const float* __restrict__ Wo,
                          float* __restrict__ wqk_hi, float* __restrict__ wqk_lo,
                          float* __restrict__ vh, float* __restrict__ oh)
{
    const int idx = blockIdx.x * 256 + threadIdx.x;  // 0 .. 512*512-1
    const int wsel = blockIdx.y;                     // 0..3
    const int n = idx & 511;        // coalesced read over n
    const int k = idx >> 9;
    const float* W; float *Th, *Tl;
    if      (wsel == 0) { W = Wq; Th = wqk_hi;             Tl = wqk_lo; }
    else if (wsel == 1) { W = Wk; Th = wqk_hi + DIM * DIM; Tl = wqk_lo + DIM * DIM; }
    else if (wsel == 2) { W = Wv; Th = vh; Tl = nullptr; }
    else                { W = Wo; Th = oh; Tl = nullptr; }
    const float w = W[(size_t)k * DIM + n];
    const float h = tf32_rna(w);
    const size_t dst = (size_t)n * DIM + permk(k);
    Th[dst] = h;
    if (Tl) Tl[dst] = tf32_rna(w - h);
}

// ---------------- softmax (rows of 2048), output tf32-rounded --------------
__global__ void __launch_bounds__(256) softmax_rows(float* __restrict__ S)
{
    const size_t row = blockIdx.x;
    float* p = S + row * (size_t)SEQ;
    const int t = threadIdx.x;
    float vals[8];
    float m = -3.402823466e38f;
#pragma unroll
    for (int i = 0; i < 8; i++) { vals[i] = p[t + i * 256]; m = fmaxf(m, vals[i]); }
    __shared__ float red[256];
    red[t] = m; __syncthreads();
#pragma unroll
    for (int s = 128; s > 0; s >>= 1) { if (t < s) red[t] = fmaxf(red[t], red[t+s]); __syncthreads(); }
    m = red[0]; __syncthreads();
    float sum = 0.0f;
#pragma unroll
    for (int i = 0; i < 8; i++) { vals[i] = __expf(vals[i] - m); sum += vals[i]; }
    red[t] = sum; __syncthreads();
#pragma unroll
    for (int s = 128; s > 0; s >>= 1) { if (t < s) red[t] += red[t+s]; __syncthreads(); }
    const float inv = 1.0f / red[0];
#pragma unroll
    for (int i = 0; i < 8; i++) p[t + i * 256] = tf32_rna(vals[i] * inv);
}

// ---------------- launcher --------------------------------------------------
extern "C" void kernel_launch(void* const* d_in, const int* in_sizes, int n_in,
                              void* d_out, int out_size)
{
    (void)in_sizes; (void)n_in; (void)out_size;
    const float* query     = (const float*)d_in[0];
    const float* key_value = (const float*)d_in[1];
    const float* Wq = (const float*)d_in[2];
    const float* bq = (const float*)d_in[3];
    const float* Wk = (const float*)d_in[4];
    const float* bk = (const float*)d_in[5];
    const float* Wv = (const float*)d_in[6];
    const float* bv = (const float*)d_in[7];
    const float* Wo = (const float*)d_in[8];
    const float* bo = (const float*)d_in[9];
    float* out = (float*)d_out;

    float *in_hi, *in_lo, *qk_hi, *qk_lo, *vt, *s, *o;
    float *wqk_hi, *wqk_lo, *wvt, *wot;
    cudaGetSymbolAddress((void**)&in_hi,  g_in_hi);
    cudaGetSymbolAddress((void**)&in_lo,  g_in_lo);
    cudaGetSymbolAddress((void**)&qk_hi,  g_qk_hi);
    cudaGetSymbolAddress((void**)&qk_lo,  g_qk_lo);
    cudaGetSymbolAddress((void**)&vt,     g_vt);
    cudaGetSymbolAddress((void**)&s,      g_s);
    cudaGetSymbolAddress((void**)&o,      g_o);
    cudaGetSymbolAddress((void**)&wqk_hi, g_wqk_hi);
    cudaGetSymbolAddress((void**)&wqk_lo, g_wqk_lo);
    cudaGetSymbolAddress((void**)&wvt,    g_wvt);
    cudaGetSymbolAddress((void**)&wot,    g_wot);

    constexpr int SM3 = 2 * 4 * TILE_B;   // 163840 B
    constexpr int SM1 = 2 * 2 * TILE_B;   // 81920 B
    cudaFuncSetAttribute(gemm_mma<3,0>, cudaFuncAttributeMaxDynamicSharedMemorySize, SM3);
    cudaFuncSetAttribute(gemm_mma<3,2>, cudaFuncAttributeMaxDynamicSharedMemorySize, SM3);
    cudaFuncSetAttribute(gemm_mma<1,1>, cudaFuncAttributeMaxDynamicSharedMemorySize, SM1);
    cudaFuncSetAttribute(gemm_mma<1,3>, cudaFuncAttributeMaxDynamicSharedMemorySize, SM1);
    cudaFuncSetAttribute(gemm_mma<1,4>, cudaFuncAttributeMaxDynamicSharedMemorySize, SM1);

    const size_t sQKV = (size_t)SEQ * DIM;
    const size_t sS   = (size_t)SEQ * SEQ;
    const size_t sVT  = (size_t)DIM * SEQ;
    const int n4 = (int)(BND / 4);
    const float* q_hi = qk_hi;
    const float* q_lo = qk_lo;
    const float* k_hi = qk_hi + BND;
    const float* k_lo = qk_lo + BND;

    // 0: fused input splits (query + key_value)
    split_two<<<(2 * n4 + 255) / 256, 256>>>((const float4*)query,
        (const float4*)key_value, in_hi, in_lo, n4);
    // 1: fused weight transposes
    {
        dim3 g((DIM * DIM) / 256, 4);
        wprep_all<<<g, 256>>>(Wq, Wk, Wv, Wo, wqk_hi, wqk_lo, wvt, wot);
    }

    // 2: G1+G2 fused: q,k projections (3xTF32, 512 thr, z = projection)
    {
        dim3 grid(DIM / 128, (BB * SEQ) / 128, 2);
        gemm_mma<3,0><<<grid, 512, SM3>>>(in_hi, in_lo, wqk_hi, wqk_lo,
            qk_hi, qk_lo, bq, bk, nullptr, DIM, DIM, DIM, DIM,
            BND, (size_t)DIM * DIM, BND, 1.0f);
    }

    // 3: G4: S = sqrt(512) * q @ k^T (3xTF32, 512 thr, batched)
    {
        dim3 grid(SEQ / 128, SEQ / 128, BB);
        gemm_mma<3,2><<<grid, 512, SM3>>>(q_hi, q_lo, k_hi, k_lo,
            s, nullptr, nullptr, nullptr, nullptr, DIM, DIM, DIM, SEQ,
            sQKV, sQKV, sS, SCALE_F);
    }

    // 4: G3: v projection -> transposed VT (1x)
    {
        dim3 grid(DIM / 128, (BB * SEQ) / 128, 1);
        gemm_mma<1,1><<<grid, 256, SM1>>>(in_hi + BND, nullptr, wvt, nullptr,
            vt, nullptr, bv, nullptr, nullptr, DIM, DIM, DIM, 0, 0, 0, 0, 1.0f);
    }

    // 5: softmax
    softmax_rows<<<BB * SEQ, 256>>>(s);

    // 6: G5: O = P @ V (1x, batched), B = VT
    {
        dim3 grid(DIM / 128, SEQ / 128, BB);
        gemm_mma<1,3><<<grid, 256, SM1>>>(s, nullptr, vt, nullptr,
            o, nullptr, nullptr, nullptr, nullptr, SEQ, SEQ, SEQ, DIM,
            sS, sVT, sQKV, 1.0f);
    }

    // 7: G6: out = query + O @ Wo + bo (1x)
    {
        dim3 grid(DIM / 128, (BB * SEQ) / 128, 1);
        gemm_mma<1,4><<<grid, 256, SM1>>>(o, nullptr, wot, nullptr,
            out, nullptr, bo, nullptr, query, DIM, DIM, DIM, DIM, 0, 0, 0, 1.0f);
    }
}

// round 9
// speedup vs baseline: 1.4349x; 1.2438x over previous
#include <cuda_runtime.h>
#include <cuda_bf16.h>
#include <cstdint>

// ===========================================================================
// AxisAttention: bf16x3 (m16n8k16) split-precision for q/k projections and
// QK^T (4 terms); single-pass tf32 (m16n8k8) for v-proj, PV, out-proj.
// B=4, N=2048, D=DA=512.
// ===========================================================================

constexpr int BB  = 4;
constexpr int SEQ = 2048;
constexpr int DIM = 512;
constexpr float SCALE_F = 22.62741699796952f;  // sqrt(512), multiplied

constexpr size_t BND = (size_t)BB * SEQ * DIM;

// ---------------- device global scratch (no runtime allocation) -----------
__device__ __nv_bfloat16 g_in_bh[2 * BND];   // [query ; key_value] bf16 hi
__device__ __nv_bfloat16 g_in_bl[2 * BND];   // bf16 lo
__device__ float         g_kv_t32[BND];      // kv tf32-rounded (old perm)
__device__ __nv_bfloat16 g_qk_bh[2 * BND];   // [q ; k] bf16 hi
__device__ __nv_bfloat16 g_qk_bl[2 * BND];
__device__ float g_vt[(size_t)BB * DIM * SEQ];
__device__ float g_s[(size_t)BB * SEQ * SEQ];
__device__ float g_o[BND];
__device__ __nv_bfloat16 g_wqk_bh[2 * DIM * DIM];
__device__ __nv_bfloat16 g_wqk_bl[2 * DIM * DIM];
__device__ float g_wvt[DIM * DIM];
__device__ float g_wot[DIM * DIM];

// ---------------- helpers ---------------------------------------------------
__device__ __forceinline__ uint32_t smem_u32(const void* p) {
    uint32_t a;
    asm("{ .reg .u64 t; cvta.to.shared.u64 t, %1; cvt.u32.u64 %0, t; }"
        : "=r"(a) : "l"(p));
    return a;
}
__device__ __forceinline__ float tf32_rna(float x) {
    uint32_t u;
    asm("cvt.rna.tf32.f32 %0, %1;" : "=r"(u) : "f"(x));
    return __uint_as_float(u);
}
__device__ __forceinline__ void cp16(uint32_t saddr, const void* g) {
    asm volatile("cp.async.cg.shared.global [%0], [%1], 16;"
                 :: "r"(saddr), "l"(g) : "memory");
}
__device__ __forceinline__ void cp_commit() {
    asm volatile("cp.async.commit_group;" ::: "memory");
}
template <int N>
__device__ __forceinline__ void cp_wait() {
    asm volatile("cp.async.wait_group %0;" :: "n"(N) : "memory");
}

// old tf32 perm within 16: (t,t+4)->(2t,2t+1) per 8-half
__device__ __forceinline__ int permk(int k) {
    const int lo = k & 7;
    return (k & ~15) | ((k & 8) + 2 * (lo & 3) + (lo >> 2));
}
// bf16 k16 perm: logical k=8e+2q+d -> phys 4q+2e+d (thread q's 4 values contiguous)
__device__ __forceinline__ int permkb(int k) {
    const int t = k & 15;
    const int q = (t & 7) >> 1, d = t & 1, e = t >> 3;
    return (k & ~15) | (4 * q + 2 * e + d);
}

// mma.sync m16n8k8 tf32
__device__ __forceinline__ void mma8(float* c, float a0, float a1, float a2,
                                     float a3, float b0, float b1) {
    asm volatile(
        "mma.sync.aligned.m16n8k8.row.col.f32.tf32.tf32.f32 "
        "{%0,%1,%2,%3}, {%4,%5,%6,%7}, {%8,%9}, {%0,%1,%2,%3};"
        : "+f"(c[0]), "+f"(c[1]), "+f"(c[2]), "+f"(c[3])
        : "r"(__float_as_uint(a0)), "r"(__float_as_uint(a1)),
          "r"(__float_as_uint(a2)), "r"(__float_as_uint(a3)),
          "r"(__float_as_uint(b0)), "r"(__float_as_uint(b1)));
}
// mma.sync m16n8k16 bf16
__device__ __forceinline__ void mma16(float* c, uint32_t a0, uint32_t a1,
                                      uint32_t a2, uint32_t a3,
                                      uint32_t b0, uint32_t b1) {
    asm volatile(
        "mma.sync.aligned.m16n8k16.row.col.f32.bf16.bf16.f32 "
        "{%0,%1,%2,%3}, {%4,%5,%6,%7}, {%8,%9}, {%0,%1,%2,%3};"
        : "+f"(c[0]), "+f"(c[1]), "+f"(c[2]), "+f"(c[3])
        : "r"(a0), "r"(a1), "r"(a2), "r"(a3), "r"(b0), "r"(b1));
}
__device__ __forceinline__ uint32_t f2u(float x) { return __float_as_uint(x); }

// ===========================================================================
// bf16 GEMM: D = alpha * A @ B^T (+bias), CTA 128x128, 512 thr, 4x4 warps,
// warp tile 32x32, K-chunk 32 (2 x k16), double-buffered cp.async.
// SMEM row: [hi 64B | lo 64B | pad 32B] = 160B stride (conflict-free).
// NTERMS: 3 = hh+hl+lh, 4 = +ll. EPI: 0 = bf16 hi/lo split out (permkb cols),
// 2 = alpha-scaled fp32 out (permk cols, for softmax/PV).
// ===========================================================================
template <int NTERMS, int EPI>
__global__ void __launch_bounds__(512, 1) gemm_bf16(
    const __nv_bfloat16* __restrict__ Ahi, const __nv_bfloat16* __restrict__ Alo,
    const __nv_bfloat16* __restrict__ Bhi, const __nv_bfloat16* __restrict__ Blo,
    void* __restrict__ Cp, void* __restrict__ C2p,
    const float* __restrict__ bias, const float* __restrict__ bias2,
    int K, int lda, int ldb, int ldc,
    size_t sA, size_t sB, size_t sC, float alpha)
{
    constexpr int IT = 2, WN = 4;
    constexpr int ROWB  = 160;
    constexpr int TILEB = 128 * ROWB;     // 20480 B
    constexpr int STAGEB = 2 * TILEB;     // 40960 B

    extern __shared__ char smc[];
    const uint32_t sb = smem_u32(smc);

    const int tid    = threadIdx.x;
    const int lane   = tid & 31;
    const int wid    = tid >> 5;
    const int warp_m = wid >> 2;      // 0..3
    const int warp_n = wid & 3;       // 0..3
    const int q      = lane & 3;
    const int n0 = blockIdx.x * 128;
    const int m0 = blockIdx.y * 128;
    const int z  = blockIdx.z;

    const float* bias_z = (EPI == 0 && z == 1) ? bias2 : bias;

    const __nv_bfloat16* A0 = Ahi + (size_t)z * sA + (size_t)m0 * lda;
    const __nv_bfloat16* A1 = Alo + (size_t)z * sA + (size_t)m0 * lda;
    const __nv_bfloat16* B0 = Bhi + (size_t)z * sB + (size_t)n0 * ldb;
    const __nv_bfloat16* B1 = Blo + (size_t)z * sB + (size_t)n0 * ldb;

    float acc[IT][WN][4];
#pragma unroll
    for (int i = 0; i < IT; i++)
#pragma unroll
        for (int j = 0; j < WN; j++)
#pragma unroll
            for (int l = 0; l < 4; l++) acc[i][j][l] = 0.0f;

    const int nch = K / 32;

    // 2048 cp16 per stage / 512 threads = 4 each
    auto load_stage = [&](int buf, int c) {
        const uint32_t st = sb + (uint32_t)buf * STAGEB;
#pragma unroll
        for (int i = 0; i < 4; i++) {
            const int idx = tid + i * 512;          // 0..2047
            const int tile = idx >> 10;             // 0: A, 1: B
            const int w    = idx & 1023;
            const int row  = w >> 3;
            const int h    = (w >> 2) & 1;          // 0: hi, 1: lo
            const int cc   = w & 3;
            const __nv_bfloat16* src =
                tile ? (h ? B1 : B0) : (h ? A1 : A0);
            const int ld = tile ? ldb : lda;
            cp16(st + (uint32_t)(tile * TILEB + row * ROWB + h * 64 + cc * 16),
                 src + (size_t)row * ld + c * 32 + cc * 8);
        }
    };

    load_stage(0, 0);
    cp_commit();

    const int arow0 = warp_m * 32 + (lane >> 2);
    const int bcol0 = warp_n * 32 + (lane >> 2);

    for (int c = 0; c < nch; c++) {
        if (c + 1 < nch) {
            load_stage((c + 1) & 1, c + 1);
            cp_commit();
            cp_wait<1>();
        } else {
            cp_wait<0>();
        }
        __syncthreads();

        const char* stg = smc + (size_t)(c & 1) * STAGEB;
        const char* Ab  = stg;
        const char* Bb  = stg + TILEB;

#pragma unroll
        for (int b = 0; b < 2; b++) {
            const int kb = b * 32 + 8 * q;
            float2 Ah0[IT], Ah1[IT], Al0[IT], Al1[IT];
#pragma unroll
            for (int i = 0; i < IT; i++) {
                const int row = arow0 + i * 16;
                Ah0[i] = *reinterpret_cast<const float2*>(Ab + row * ROWB + kb);
                Ah1[i] = *reinterpret_cast<const float2*>(Ab + (row + 8) * ROWB + kb);
                Al0[i] = *reinterpret_cast<const float2*>(Ab + row * ROWB + 64 + kb);
                Al1[i] = *reinterpret_cast<const float2*>(Ab + (row + 8) * ROWB + 64 + kb);
            }
            float2 Bh[WN], Bl[WN];
#pragma unroll
            for (int j = 0; j < WN; j++) {
                const int col = bcol0 + j * 8;
                Bh[j] = *reinterpret_cast<const float2*>(Bb + col * ROWB + kb);
                Bl[j] = *reinterpret_cast<const float2*>(Bb + col * ROWB + 64 + kb);
            }
            // hi * hi
#pragma unroll
            for (int i = 0; i < IT; i++)
#pragma unroll
                for (int j = 0; j < WN; j++)
                    mma16(acc[i][j], f2u(Ah0[i].x), f2u(Ah1[i].x),
                          f2u(Ah0[i].y), f2u(Ah1[i].y), f2u(Bh[j].x), f2u(Bh[j].y));
            // hi * lo
#pragma unroll
            for (int i = 0; i < IT; i++)
#pragma unroll
                for (int j = 0; j < WN; j++)
                    mma16(acc[i][j], f2u(Ah0[i].x), f2u(Ah1[i].x),
                          f2u(Ah0[i].y), f2u(Ah1[i].y), f2u(Bl[j].x), f2u(Bl[j].y));
            // lo * hi
#pragma unroll
            for (int i = 0; i < IT; i++)
#pragma unroll
                for (int j = 0; j < WN; j++)
                    mma16(acc[i][j], f2u(Al0[i].x), f2u(Al1[i].x),
                          f2u(Al0[i].y), f2u(Al1[i].y), f2u(Bh[j].x), f2u(Bh[j].y));
            if (NTERMS == 4) {  // lo * lo
#pragma unroll
                for (int i = 0; i < IT; i++)
#pragma unroll
                    for (int j = 0; j < WN; j++)
                        mma16(acc[i][j], f2u(Al0[i].x), f2u(Al1[i].x),
                              f2u(Al0[i].y), f2u(Al1[i].y), f2u(Bl[j].x), f2u(Bl[j].y));
            }
        }
        __syncthreads();
    }

    // ---------------- epilogue ----------------
#pragma unroll
    for (int i = 0; i < IT; i++) {
#pragma unroll
        for (int j = 0; j < WN; j++) {
            const float* a4 = acc[i][j];
            const int r0 = m0 + warp_m * 32 + i * 16 + (lane >> 2);
            const int c0 = n0 + warp_n * 32 + j * 8 + 2 * q;
            if (EPI == 0) {            // split to bf16 hi/lo + bias, permkb cols
                __nv_bfloat16* Cz  = (__nv_bfloat16*)Cp  + (size_t)z * sC;
                __nv_bfloat16* C2z = (__nv_bfloat16*)C2p + (size_t)z * sC;
                const float bx = bias_z[c0], by = bias_z[c0 + 1];
                const int p0 = permkb(c0), p1 = permkb(c0 + 1);
                const float v[4] = {a4[0] + bx, a4[1] + by, a4[2] + bx, a4[3] + by};
                const int rr[4] = {r0, r0, r0 + 8, r0 + 8};
                const int pp[4] = {p0, p1, p0, p1};
#pragma unroll
                for (int u = 0; u < 4; u++) {
                    const __nv_bfloat16 h = __float2bfloat16(v[u]);
                    Cz[(size_t)rr[u] * ldc + pp[u]] = h;
                    C2z[(size_t)rr[u] * ldc + pp[u]] =
                        __float2bfloat16(v[u] - __bfloat162float(h));
                }
            } else {                   // alpha-scaled fp32, permk cols (scores)
                float* Cz = (float*)Cp + (size_t)z * sC;
                const int p0 = permk(c0), p1 = permk(c0 + 1);
                Cz[(size_t)r0 * ldc + p0]       = alpha * a4[0];
                Cz[(size_t)r0 * ldc + p1]       = alpha * a4[1];
                Cz[(size_t)(r0 + 8) * ldc + p0] = alpha * a4[2];
                Cz[(size_t)(r0 + 8) * ldc + p1] = alpha * a4[3];
            }
        }
    }
}

// ===========================================================================
// tf32 1-pass GEMM (unchanged from best config): CTA 128x128, 256 thr occ 2,
// warp 64x32 (IT=4), K-chunk 32, LDW 40.
// EPI: 1=transposed VT+bias (perm seq), 3=plain tf32 (perm cols),
// 4=bias+residual.
// ===========================================================================
constexpr int LDW    = 40;
constexpr int TILE_F = 128 * LDW;
constexpr int TILE_B = TILE_F * 4;

__device__ __forceinline__ void load_tile32(
    uint32_t sbase, const float* __restrict__ g, int ld, int tid)
{
#pragma unroll
    for (int i = 0; i < 4; i++) {
        const int f  = tid + i * 256;
        const int r  = f >> 3;
        const int c4 = (f & 7) << 2;
        cp16(sbase + (uint32_t)(r * LDW + c4) * 4, g + (size_t)r * ld + c4);
    }
}

template <int EPI>
__global__ void __launch_bounds__(256, 2) gemm_t32(
    const float* __restrict__ A, const float* __restrict__ B,
    float* __restrict__ C,
    const float* __restrict__ bias, const float* __restrict__ resid,
    int K, int lda, int ldb, int ldc,
    size_t sA, size_t sB, size_t sC)
{
    constexpr int IT = 4;
    extern __shared__ float smf[];
    const uint32_t sb = smem_u32(smf);

    const int tid    = threadIdx.x;
    const int lane   = tid & 31;
    const int wid    = tid >> 5;
    const int warp_m = wid >> 2;
    const int warp_n = wid & 3;
    const int n0 = blockIdx.x * 128;
    const int m0 = blockIdx.y * 128;
    const int z  = blockIdx.z;

    const float* A0 = A + (size_t)z * sA + (size_t)m0 * lda;
    const float* B0 = B + (size_t)z * sB + (size_t)n0 * ldb;

    float acc[IT][4][4];
#pragma unroll
    for (int i = 0; i < IT; i++)
#pragma unroll
        for (int j = 0; j < 4; j++)
#pragma unroll
            for (int l = 0; l < 4; l++) acc[i][j][l] = 0.0f;

    const int nch = K / 32;

    auto load_stage = [&](int buf, int c) {
        const uint32_t st = sb + (uint32_t)buf * 2 * TILE_B;
        load_tile32(st,          A0 + c * 32, lda, tid);
        load_tile32(st + TILE_B, B0 + c * 32, ldb, tid);
    };

    load_stage(0, 0);
    cp_commit();

    const int arow0 = warp_m * 64 + (lane >> 2);
    const int bcol0 = warp_n * 32 + (lane >> 2);
    const int kq2   = 2 * (lane & 3);

    for (int c = 0; c < nch; c++) {
        if (c + 1 < nch) {
            load_stage((c + 1) & 1, c + 1);
            cp_commit();
            cp_wait<1>();
        } else {
            cp_wait<0>();
        }
        __syncthreads();

        const float* st  = smf + (size_t)(c & 1) * 2 * TILE_F;
        const float* Ath = st;
        const float* Bth = st + TILE_F;

#pragma unroll
        for (int s = 0; s < 4; s++) {
            const int ko = s * 8 + kq2;
            float2 a0[IT], a1[IT], b0[4];
#pragma unroll
            for (int i = 0; i < IT; i++) {
                a0[i] = *reinterpret_cast<const float2*>(
                    Ath + (size_t)(arow0 + i * 16) * LDW + ko);
                a1[i] = *reinterpret_cast<const float2*>(
                    Ath + (size_t)(arow0 + i * 16 + 8) * LDW + ko);
            }
#pragma unroll
            for (int j = 0; j < 4; j++)
                b0[j] = *reinterpret_cast<const float2*>(
                    Bth + (size_t)(bcol0 + j * 8) * LDW + ko);
#pragma unroll
            for (int i = 0; i < IT; i++)
#pragma unroll
                for (int j = 0; j < 4; j++)
                    mma8(acc[i][j], a0[i].x, a1[i].x, a0[i].y, a1[i].y,
                         b0[j].x, b0[j].y);
        }
        __syncthreads();
    }

    float* Cz = C + (size_t)z * sC;
#pragma unroll
    for (int i = 0; i < IT; i++) {
#pragma unroll
        for (int j = 0; j < 4; j++) {
            const float* a4 = acc[i][j];
            const int r0 = m0 + warp_m * 64 + i * 16 + (lane >> 2);
            const int c0 = n0 + warp_n * 32 + j * 8 + 2 * (lane & 3);
            if (EPI == 1) {            // transposed VT[b][dim][seq], perm seq
                const float bx = bias[c0], by = bias[c0 + 1];
                const int b0i = r0 >> 11,        sx0 = permk(r0 & (SEQ - 1));
                const int b1i = (r0 + 8) >> 11,  sx1 = permk((r0 + 8) & (SEQ - 1));
                float* p0 = C + (size_t)b0i * DIM * SEQ;
                float* p1 = C + (size_t)b1i * DIM * SEQ;
                p0[(size_t)c0 * SEQ + sx0]       = tf32_rna(a4[0] + bx);
                p0[(size_t)(c0 + 1) * SEQ + sx0] = tf32_rna(a4[1] + by);
                p1[(size_t)c0 * SEQ + sx1]       = tf32_rna(a4[2] + bx);
                p1[(size_t)(c0 + 1) * SEQ + sx1] = tf32_rna(a4[3] + by);
            } else if (EPI == 3) {     // plain tf32-rounded, perm cols (O)
                const int p0 = permk(c0), p1 = permk(c0 + 1);
                Cz[(size_t)r0 * ldc + p0]       = tf32_rna(a4[0]);
                Cz[(size_t)r0 * ldc + p1]       = tf32_rna(a4[1]);
                Cz[(size_t)(r0 + 8) * ldc + p0] = tf32_rna(a4[2]);
                Cz[(size_t)(r0 + 8) * ldc + p1] = tf32_rna(a4[3]);
            } else {                   // bias + residual (final out), no perm
                const float bx = bias[c0], by = bias[c0 + 1];
                const float2 rs0 = *reinterpret_cast<const float2*>(
                    &resid[(size_t)r0 * ldc + c0]);
                const float2 rs1 = *reinterpret_cast<const float2*>(
                    &resid[(size_t)(r0 + 8) * ldc + c0]);
                float2 v0, v1;
                v0.x = a4[0] + bx + rs0.x; v0.y = a4[1] + by + rs0.y;
                v1.x = a4[2] + bx + rs1.x; v1.y = a4[3] + by + rs1.y;
                *reinterpret_cast<float2*>(&Cz[(size_t)r0 * ldc + c0]) = v0;
                *reinterpret_cast<float2*>(&Cz[(size_t)(r0 + 8) * ldc + c0]) = v1;
            }
        }
    }
}

// ---------------- prep: fp32 -> bf16 hi/lo (permkb) [+ tf32 fp32 (permk)] --
__global__ void split_bf16(const float4* __restrict__ src,
                           __nv_bfloat16* __restrict__ dh,
                           __nv_bfloat16* __restrict__ dl,
                           float* __restrict__ d32, int n4)
{
    const int id = blockIdx.x * 256 + threadIdx.x;
    if (id >= n4) return;
    const float4 v = src[id];
    const int e0 = id * 4;
    const int base = e0 & ~511;
    const float vv[4] = {v.x, v.y, v.z, v.w};
#pragma unroll
    for (int u = 0; u < 4; u++) {
        const int k = (e0 + u) & 511;
        const float x = vv[u];
        const __nv_bfloat16 h = __float2bfloat16(x);
        const int pb = permkb(k);
        dh[base + pb] = h;
        dl[base + pb] = __float2bfloat16(x - __bfloat162float(h));
        if (d32) d32[base + permk(k)] = tf32_rna(x);
    }
}

// ---------------- prep: weight transposes ----------------------------------
__global__ void wprep_all(const float* __restrict__ Wq, const float* __restrict__ Wk,
                          const float* __restrict__ Wv, const float* __restrict__ Wo,
                          __nv_bfloat16* __restrict__ wbh,
                          __nv_bfloat16* __restrict__ wbl,
                          float* __restrict__ vh, float* __restrict__ oh)
{
    const int idx = blockIdx.x * 256 + threadIdx.x;
    const int wsel = blockIdx.y;
    const int n = idx & 511;
    const int k = idx >> 9;
    if (wsel < 2) {
        const float w = (wsel ? Wk : Wq)[(size_t)k * DIM + n];
        const __nv_bfloat16 h = __float2bfloat16(w);
        const size_t dst = (size_t)wsel * DIM * DIM + (size_t)n * DIM + permkb(k);
        wbh[dst] = h;
        wbl[dst] = __float2bfloat16(w - __bfloat162float(h));
    } else {
        const float w = (wsel == 2 ? Wv : Wo)[(size_t)k * DIM + n];
        float* T = (wsel == 2) ? vh : oh;
        T[(size_t)n * DIM + permk(k)] = tf32_rna(w);
    }
}

// ---------------- softmax (rows of 2048), output tf32-rounded --------------
__global__ void __launch_bounds__(256) softmax_rows(float* __restrict__ S)
{
    const size_t row = blockIdx.x;
    float* p = S + row * (size_t)SEQ;
    const int t = threadIdx.x;
    float vals[8];
    float m = -3.402823466e38f;
#pragma unroll
    for (int i = 0; i < 8; i++) { vals[i] = p[t + i * 256]; m = fmaxf(m, vals[i]); }
    __shared__ float red[256];
    red[t] = m; __syncthreads();
#pragma unroll
    for (int s = 128; s > 0; s >>= 1) { if (t < s) red[t] = fmaxf(red[t], red[t+s]); __syncthreads(); }
    m = red[0]; __syncthreads();
    float sum = 0.0f;
#pragma unroll
    for (int i = 0; i < 8; i++) { vals[i] = __expf(vals[i] - m); sum += vals[i]; }
    red[t] = sum; __syncthreads();
#pragma unroll
    for (int s = 128; s > 0; s >>= 1) { if (t < s) red[t] += red[t+s]; __syncthreads(); }
    const float inv = 1.0f / red[0];
#pragma unroll
    for (int i = 0; i < 8; i++) p[t + i * 256] = tf32_rna(vals[i] * inv);
}

// ---------------- launcher --------------------------------------------------
extern "C" void kernel_launch(void* const* d_in, const int* in_sizes, int n_in,
                              void* d_out, int out_size)
{
    (void)in_sizes; (void)n_in; (void)out_size;
    const float* query     = (const float*)d_in[0];
    const float* key_value = (const float*)d_in[1];
    const float* Wq = (const float*)d_in[2];
    const float* bq = (const float*)d_in[3];
    const float* Wk = (const float*)d_in[4];
    const float* bk = (const float*)d_in[5];
    const float* Wv = (const float*)d_in[6];
    const float* bv = (const float*)d_in[7];
    const float* Wo = (const float*)d_in[8];
    const float* bo = (const float*)d_in[9];
    float* out = (float*)d_out;

    __nv_bfloat16 *in_bh, *in_bl, *qk_bh, *qk_bl, *wbh, *wbl;
    float *kv_t32, *vt, *s, *o, *wvt, *wot;
    cudaGetSymbolAddress((void**)&in_bh,  g_in_bh);
    cudaGetSymbolAddress((void**)&in_bl,  g_in_bl);
    cudaGetSymbolAddress((void**)&kv_t32, g_kv_t32);
    cudaGetSymbolAddress((void**)&qk_bh,  g_qk_bh);
    cudaGetSymbolAddress((void**)&qk_bl,  g_qk_bl);
    cudaGetSymbolAddress((void**)&vt,     g_vt);
    cudaGetSymbolAddress((void**)&s,      g_s);
    cudaGetSymbolAddress((void**)&o,      g_o);
    cudaGetSymbolAddress((void**)&wbh,    g_wqk_bh);
    cudaGetSymbolAddress((void**)&wbl,    g_wqk_bl);
    cudaGetSymbolAddress((void**)&wvt,    g_wvt);
    cudaGetSymbolAddress((void**)&wot,    g_wot);

    constexpr int SMB = 2 * 2 * 128 * 160;   // bf16 kernels: 81920 B
    constexpr int SM1 = 2 * 2 * TILE_B;      // tf32 kernels: 81920 B
    cudaFuncSetAttribute(gemm_bf16<3,0>, cudaFuncAttributeMaxDynamicSharedMemorySize, SMB);
    cudaFuncSetAttribute(gemm_bf16<4,2>, cudaFuncAttributeMaxDynamicSharedMemorySize, SMB);
    cudaFuncSetAttribute(gemm_t32<1>, cudaFuncAttributeMaxDynamicSharedMemorySize, SM1);
    cudaFuncSetAttribute(gemm_t32<3>, cudaFuncAttributeMaxDynamicSharedMemorySize, SM1);
    cudaFuncSetAttribute(gemm_t32<4>, cudaFuncAttributeMaxDynamicSharedMemorySize, SM1);

    const size_t sQKV = (size_t)SEQ * DIM;
    const size_t sS   = (size_t)SEQ * SEQ;
    const size_t sVT  = (size_t)DIM * SEQ;
    const int n4 = (int)(BND / 4);

    // 0/1: input splits
    split_bf16<<<n4 / 256, 256>>>((const float4*)query, in_bh, in_bl, nullptr, n4);
    split_bf16<<<n4 / 256, 256>>>((const float4*)key_value, in_bh + BND,
                                  in_bl + BND, kv_t32, n4);
    // 2: weight transposes
    {
        dim3 g((DIM * DIM) / 256, 4);
        wprep_all<<<g, 256>>>(Wq, Wk, Wv, Wo, wbh, wbl, wvt, wot);
    }
    // 3: v projection -> transposed VT (tf32 1-pass)
    {
        dim3 grid(DIM / 128, (BB * SEQ) / 128, 1);
        gemm_t32<1><<<grid, 256, SM1>>>(kv_t32, wvt, vt, bv, nullptr,
                                        DIM, DIM, DIM, 0, 0, 0, 0);
    }
    // 4: q,k projections fused (bf16x3, z = projection)
    {
        dim3 grid(DIM / 128, (BB * SEQ) / 128, 2);
        gemm_bf16<3,0><<<grid, 512, SMB>>>(in_bh, in_bl, wbh, wbl,
            qk_bh, qk_bl, bq, bk, DIM, DIM, DIM, DIM,
            BND, (size_t)DIM * DIM, BND, 1.0f);
    }
    // 5: S = sqrt(512) * q @ k^T (bf16x4, batched)  [ncu launch index 5]
    {
        dim3 grid(SEQ / 128, SEQ / 128, BB);
        gemm_bf16<4,2><<<grid, 512, SMB>>>(qk_bh, qk_bl, qk_bh + BND, qk_bl + BND,
            s, nullptr, nullptr, nullptr, DIM, DIM, DIM, SEQ,
            sQKV, sQKV, sS, SCALE_F);
    }
    // 6: softmax
    softmax_rows<<<BB * SEQ, 256>>>(s);
    // 7: O = P @ V (tf32 1-pass, batched)
    {
        dim3 grid(DIM / 128, SEQ / 128, BB);
        gemm_t32<3><<<grid, 256, SM1>>>(s, vt, o, nullptr, nullptr,
                                        SEQ, SEQ, SEQ, DIM, sS, sVT, sQKV);
    }
    // 8: out = query + O @ Wo + bo (tf32 1-pass)
    {
        dim3 grid(DIM / 128, (BB * SEQ) / 128, 1);
        gemm_t32<4><<<grid, 256, SM1>>>(o, wot, out, bo, query,
                                        DIM, DIM, DIM, DIM, 0, 0, 0);
    }
}

// round 10
// speedup vs baseline: 1.5011x; 1.0461x over previous
#include <cuda_runtime.h>
#include <cuda_bf16.h>
#include <cstdint>

// ===========================================================================
// AxisAttention: bf16x3 (m16n8k16) split-precision for q/k projections AND
// QK^T (lo*lo dropped: contributes <1e-5 rel); single-pass tf32 (m16n8k8)
// for v-proj, PV, out-proj. B=4, N=2048, D=DA=512.
// ===========================================================================

constexpr int BB  = 4;
constexpr int SEQ = 2048;
constexpr int DIM = 512;
constexpr float SCALE_F = 22.62741699796952f;  // sqrt(512), multiplied

constexpr size_t BND = (size_t)BB * SEQ * DIM;

// ---------------- device global scratch (no runtime allocation) -----------
__device__ __nv_bfloat16 g_in_bh[2 * BND];   // [query ; key_value] bf16 hi
__device__ __nv_bfloat16 g_in_bl[2 * BND];   // bf16 lo
__device__ float         g_kv_t32[BND];      // kv tf32-rounded (old perm)
__device__ __nv_bfloat16 g_qk_bh[2 * BND];   // [q ; k] bf16 hi
__device__ __nv_bfloat16 g_qk_bl[2 * BND];
__device__ float g_vt[(size_t)BB * DIM * SEQ];
__device__ float g_s[(size_t)BB * SEQ * SEQ];
__device__ float g_o[BND];
__device__ __nv_bfloat16 g_wqk_bh[2 * DIM * DIM];
__device__ __nv_bfloat16 g_wqk_bl[2 * DIM * DIM];
__device__ float g_wvt[DIM * DIM];
__device__ float g_wot[DIM * DIM];

// ---------------- helpers ---------------------------------------------------
__device__ __forceinline__ uint32_t smem_u32(const void* p) {
    uint32_t a;
    asm("{ .reg .u64 t; cvta.to.shared.u64 t, %1; cvt.u32.u64 %0, t; }"
        : "=r"(a) : "l"(p));
    return a;
}
__device__ __forceinline__ float tf32_rna(float x) {
    uint32_t u;
    asm("cvt.rna.tf32.f32 %0, %1;" : "=r"(u) : "f"(x));
    return __uint_as_float(u);
}
__device__ __forceinline__ void cp16(uint32_t saddr, const void* g) {
    asm volatile("cp.async.cg.shared.global [%0], [%1], 16;"
                 :: "r"(saddr), "l"(g) : "memory");
}
__device__ __forceinline__ void cp_commit() {
    asm volatile("cp.async.commit_group;" ::: "memory");
}
template <int N>
__device__ __forceinline__ void cp_wait() {
    asm volatile("cp.async.wait_group %0;" :: "n"(N) : "memory");
}

// old tf32 perm within 16: (t,t+4)->(2t,2t+1) per 8-half
__device__ __forceinline__ int permk(int k) {
    const int lo = k & 7;
    return (k & ~15) | ((k & 8) + 2 * (lo & 3) + (lo >> 2));
}
// bf16 k16 perm: logical k=8e+2q+d -> phys 4q+2e+d
__device__ __forceinline__ int permkb(int k) {
    const int t = k & 15;
    const int q = (t & 7) >> 1, d = t & 1, e = t >> 3;
    return (k & ~15) | (4 * q + 2 * e + d);
}

// mma.sync m16n8k8 tf32
__device__ __forceinline__ void mma8(float* c, float a0, float a1, float a2,
                                     float a3, float b0, float b1) {
    asm volatile(
        "mma.sync.aligned.m16n8k8.row.col.f32.tf32.tf32.f32 "
        "{%0,%1,%2,%3}, {%4,%5,%6,%7}, {%8,%9}, {%0,%1,%2,%3};"
        : "+f"(c[0]), "+f"(c[1]), "+f"(c[2]), "+f"(c[3])
        : "r"(__float_as_uint(a0)), "r"(__float_as_uint(a1)),
          "r"(__float_as_uint(a2)), "r"(__float_as_uint(a3)),
          "r"(__float_as_uint(b0)), "r"(__float_as_uint(b1)));
}
// mma.sync m16n8k16 bf16
__device__ __forceinline__ void mma16(float* c, uint32_t a0, uint32_t a1,
                                      uint32_t a2, uint32_t a3,
                                      uint32_t b0, uint32_t b1) {
    asm volatile(
        "mma.sync.aligned.m16n8k16.row.col.f32.bf16.bf16.f32 "
        "{%0,%1,%2,%3}, {%4,%5,%6,%7}, {%8,%9}, {%0,%1,%2,%3};"
        : "+f"(c[0]), "+f"(c[1]), "+f"(c[2]), "+f"(c[3])
        : "r"(a0), "r"(a1), "r"(a2), "r"(a3), "r"(b0), "r"(b1));
}
__device__ __forceinline__ uint32_t f2u(float x) { return __float_as_uint(x); }

// ===========================================================================
// bf16 GEMM: D = alpha * A @ B^T (+bias), CTA 128x128, 512 thr, 4x4 warps,
// warp tile 32x32, K-chunk 32 (2 x k16), double-buffered cp.async.
// SMEM row: [hi 64B | lo 64B | pad 32B] = 160B stride.
// 3 terms: hh + hl + lh. EPI: 0 = bf16 hi/lo split out (permkb cols),
// 2 = alpha-scaled fp32 out (permk cols, for softmax/PV).
// ===========================================================================
template <int EPI>
__global__ void __launch_bounds__(512, 1) gemm_bf16(
    const __nv_bfloat16* __restrict__ Ahi, const __nv_bfloat16* __restrict__ Alo,
    const __nv_bfloat16* __restrict__ Bhi, const __nv_bfloat16* __restrict__ Blo,
    void* __restrict__ Cp, void* __restrict__ C2p,
    const float* __restrict__ bias, const float* __restrict__ bias2,
    int K, int lda, int ldb, int ldc,
    size_t sA, size_t sB, size_t sC, float alpha)
{
    constexpr int IT = 2, WN = 4;
    constexpr int ROWB  = 160;
    constexpr int TILEB = 128 * ROWB;     // 20480 B
    constexpr int STAGEB = 2 * TILEB;     // 40960 B

    extern __shared__ char smc[];
    const uint32_t sb = smem_u32(smc);

    const int tid    = threadIdx.x;
    const int lane   = tid & 31;
    const int wid    = tid >> 5;
    const int warp_m = wid >> 2;
    const int warp_n = wid & 3;
    const int q      = lane & 3;
    const int n0 = blockIdx.x * 128;
    const int m0 = blockIdx.y * 128;
    const int z  = blockIdx.z;

    const float* bias_z = (EPI == 0 && z == 1) ? bias2 : bias;

    const __nv_bfloat16* A0 = Ahi + (size_t)z * sA + (size_t)m0 * lda;
    const __nv_bfloat16* A1 = Alo + (size_t)z * sA + (size_t)m0 * lda;
    const __nv_bfloat16* B0 = Bhi + (size_t)z * sB + (size_t)n0 * ldb;
    const __nv_bfloat16* B1 = Blo + (size_t)z * sB + (size_t)n0 * ldb;

    float acc[IT][WN][4];
#pragma unroll
    for (int i = 0; i < IT; i++)
#pragma unroll
        for (int j = 0; j < WN; j++)
#pragma unroll
            for (int l = 0; l < 4; l++) acc[i][j][l] = 0.0f;

    const int nch = K / 32;

    auto load_stage = [&](int buf, int c) {
        const uint32_t st = sb + (uint32_t)buf * STAGEB;
#pragma unroll
        for (int i = 0; i < 4; i++) {
            const int idx = tid + i * 512;
            const int tile = idx >> 10;
            const int w    = idx & 1023;
            const int row  = w >> 3;
            const int h    = (w >> 2) & 1;
            const int cc   = w & 3;
            const __nv_bfloat16* src =
                tile ? (h ? B1 : B0) : (h ? A1 : A0);
            const int ld = tile ? ldb : lda;
            cp16(st + (uint32_t)(tile * TILEB + row * ROWB + h * 64 + cc * 16),
                 src + (size_t)row * ld + c * 32 + cc * 8);
        }
    };

    load_stage(0, 0);
    cp_commit();

    const int arow0 = warp_m * 32 + (lane >> 2);
    const int bcol0 = warp_n * 32 + (lane >> 2);

    for (int c = 0; c < nch; c++) {
        if (c + 1 < nch) {
            load_stage((c + 1) & 1, c + 1);
            cp_commit();
            cp_wait<1>();
        } else {
            cp_wait<0>();
        }
        __syncthreads();

        const char* stg = smc + (size_t)(c & 1) * STAGEB;
        const char* Ab  = stg;
        const char* Bb  = stg + TILEB;

#pragma unroll
        for (int b = 0; b < 2; b++) {
            const int kb = b * 32 + 8 * q;
            float2 Ah0[IT], Ah1[IT], Al0[IT], Al1[IT];
#pragma unroll
            for (int i = 0; i < IT; i++) {
                const int row = arow0 + i * 16;
                Ah0[i] = *reinterpret_cast<const float2*>(Ab + row * ROWB + kb);
                Ah1[i] = *reinterpret_cast<const float2*>(Ab + (row + 8) * ROWB + kb);
                Al0[i] = *reinterpret_cast<const float2*>(Ab + row * ROWB + 64 + kb);
                Al1[i] = *reinterpret_cast<const float2*>(Ab + (row + 8) * ROWB + 64 + kb);
            }
            float2 Bh[WN], Bl[WN];
#pragma unroll
            for (int j = 0; j < WN; j++) {
                const int col = bcol0 + j * 8;
                Bh[j] = *reinterpret_cast<const float2*>(Bb + col * ROWB + kb);
                Bl[j] = *reinterpret_cast<const float2*>(Bb + col * ROWB + 64 + kb);
            }
            // hi * hi
#pragma unroll
            for (int i = 0; i < IT; i++)
#pragma unroll
                for (int j = 0; j < WN; j++)
                    mma16(acc[i][j], f2u(Ah0[i].x), f2u(Ah1[i].x),
                          f2u(Ah0[i].y), f2u(Ah1[i].y), f2u(Bh[j].x), f2u(Bh[j].y));
            // hi * lo
#pragma unroll
            for (int i = 0; i < IT; i++)
#pragma unroll
                for (int j = 0; j < WN; j++)
                    mma16(acc[i][j], f2u(Ah0[i].x), f2u(Ah1[i].x),
                          f2u(Ah0[i].y), f2u(Ah1[i].y), f2u(Bl[j].x), f2u(Bl[j].y));
            // lo * hi
#pragma unroll
            for (int i = 0; i < IT; i++)
#pragma unroll
                for (int j = 0; j < WN; j++)
                    mma16(acc[i][j], f2u(Al0[i].x), f2u(Al1[i].x),
                          f2u(Al0[i].y), f2u(Al1[i].y), f2u(Bh[j].x), f2u(Bh[j].y));
        }
        __syncthreads();
    }

    // ---------------- epilogue ----------------
#pragma unroll
    for (int i = 0; i < IT; i++) {
#pragma unroll
        for (int j = 0; j < WN; j++) {
            const float* a4 = acc[i][j];
            const int r0 = m0 + warp_m * 32 + i * 16 + (lane >> 2);
            const int c0 = n0 + warp_n * 32 + j * 8 + 2 * q;
            if (EPI == 0) {            // split to bf16 hi/lo + bias, permkb cols
                __nv_bfloat16* Cz  = (__nv_bfloat16*)Cp  + (size_t)z * sC;
                __nv_bfloat16* C2z = (__nv_bfloat16*)C2p + (size_t)z * sC;
                const float bx = bias_z[c0], by = bias_z[c0 + 1];
                const int p0 = permkb(c0), p1 = permkb(c0 + 1);
                const float v[4] = {a4[0] + bx, a4[1] + by, a4[2] + bx, a4[3] + by};
                const int rr[4] = {r0, r0, r0 + 8, r0 + 8};
                const int pp[4] = {p0, p1, p0, p1};
#pragma unroll
                for (int u = 0; u < 4; u++) {
                    const __nv_bfloat16 h = __float2bfloat16(v[u]);
                    Cz[(size_t)rr[u] * ldc + pp[u]] = h;
                    C2z[(size_t)rr[u] * ldc + pp[u]] =
                        __float2bfloat16(v[u] - __bfloat162float(h));
                }
            } else {                   // alpha-scaled fp32, permk cols (scores)
                float* Cz = (float*)Cp + (size_t)z * sC;
                const int p0 = permk(c0), p1 = permk(c0 + 1);
                Cz[(size_t)r0 * ldc + p0]       = alpha * a4[0];
                Cz[(size_t)r0 * ldc + p1]       = alpha * a4[1];
                Cz[(size_t)(r0 + 8) * ldc + p0] = alpha * a4[2];
                Cz[(size_t)(r0 + 8) * ldc + p1] = alpha * a4[3];
            }
        }
    }
}

// ===========================================================================
// tf32 1-pass GEMM: CTA 128x128, 256 thr occ 2, warp 64x32 (IT=4), K-chunk 32.
// EPI: 1=transposed VT+bias (perm seq), 3=plain tf32 (perm cols),
// 4=bias+residual.
// ===========================================================================
constexpr int LDW    = 40;
constexpr int TILE_F = 128 * LDW;
constexpr int TILE_B = TILE_F * 4;

__device__ __forceinline__ void load_tile32(
    uint32_t sbase, const float* __restrict__ g, int ld, int tid)
{
#pragma unroll
    for (int i = 0; i < 4; i++) {
        const int f  = tid + i * 256;
        const int r  = f >> 3;
        const int c4 = (f & 7) << 2;
        cp16(sbase + (uint32_t)(r * LDW + c4) * 4, g + (size_t)r * ld + c4);
    }
}

template <int EPI>
__global__ void __launch_bounds__(256, 2) gemm_t32(
    const float* __restrict__ A, const float* __restrict__ B,
    float* __restrict__ C,
    const float* __restrict__ bias, const float* __restrict__ resid,
    int K, int lda, int ldb, int ldc,
    size_t sA, size_t sB, size_t sC)
{
    constexpr int IT = 4;
    extern __shared__ float smf[];
    const uint32_t sb = smem_u32(smf);

    const int tid    = threadIdx.x;
    const int lane   = tid & 31;
    const int wid    = tid >> 5;
    const int warp_m = wid >> 2;
    const int warp_n = wid & 3;
    const int n0 = blockIdx.x * 128;
    const int m0 = blockIdx.y * 128;
    const int z  = blockIdx.z;

    const float* A0 = A + (size_t)z * sA + (size_t)m0 * lda;
    const float* B0 = B + (size_t)z * sB + (size_t)n0 * ldb;

    float acc[IT][4][4];
#pragma unroll
    for (int i = 0; i < IT; i++)
#pragma unroll
        for (int j = 0; j < 4; j++)
#pragma unroll
            for (int l = 0; l < 4; l++) acc[i][j][l] = 0.0f;

    const int nch = K / 32;

    auto load_stage = [&](int buf, int c) {
        const uint32_t st = sb + (uint32_t)buf * 2 * TILE_B;
        load_tile32(st,          A0 + c * 32, lda, tid);
        load_tile32(st + TILE_B, B0 + c * 32, ldb, tid);
    };

    load_stage(0, 0);
    cp_commit();

    const int arow0 = warp_m * 64 + (lane >> 2);
    const int bcol0 = warp_n * 32 + (lane >> 2);
    const int kq2   = 2 * (lane & 3);

    for (int c = 0; c < nch; c++) {
        if (c + 1 < nch) {
            load_stage((c + 1) & 1, c + 1);
            cp_commit();
            cp_wait<1>();
        } else {
            cp_wait<0>();
        }
        __syncthreads();

        const float* st  = smf + (size_t)(c & 1) * 2 * TILE_F;
        const float* Ath = st;
        const float* Bth = st + TILE_F;

#pragma unroll
        for (int s = 0; s < 4; s++) {
            const int ko = s * 8 + kq2;
            float2 a0[IT], a1[IT], b0[4];
#pragma unroll
            for (int i = 0; i < IT; i++) {
                a0[i] = *reinterpret_cast<const float2*>(
                    Ath + (size_t)(arow0 + i * 16) * LDW + ko);
                a1[i] = *reinterpret_cast<const float2*>(
                    Ath + (size_t)(arow0 + i * 16 + 8) * LDW + ko);
            }
#pragma unroll
            for (int j = 0; j < 4; j++)
                b0[j] = *reinterpret_cast<const float2*>(
                    Bth + (size_t)(bcol0 + j * 8) * LDW + ko);
#pragma unroll
            for (int i = 0; i < IT; i++)
#pragma unroll
                for (int j = 0; j < 4; j++)
                    mma8(acc[i][j], a0[i].x, a1[i].x, a0[i].y, a1[i].y,
                         b0[j].x, b0[j].y);
        }
        __syncthreads();
    }

    float* Cz = C + (size_t)z * sC;
#pragma unroll
    for (int i = 0; i < IT; i++) {
#pragma unroll
        for (int j = 0; j < 4; j++) {
            const float* a4 = acc[i][j];
            const int r0 = m0 + warp_m * 64 + i * 16 + (lane >> 2);
            const int c0 = n0 + warp_n * 32 + j * 8 + 2 * (lane & 3);
            if (EPI == 1) {
                const float bx = bias[c0], by = bias[c0 + 1];
                const int b0i = r0 >> 11,        sx0 = permk(r0 & (SEQ - 1));
                const int b1i = (r0 + 8) >> 11,  sx1 = permk((r0 + 8) & (SEQ - 1));
                float* p0 = C + (size_t)b0i * DIM * SEQ;
                float* p1 = C + (size_t)b1i * DIM * SEQ;
                p0[(size_t)c0 * SEQ + sx0]       = tf32_rna(a4[0] + bx);
                p0[(size_t)(c0 + 1) * SEQ + sx0] = tf32_rna(a4[1] + by);
                p1[(size_t)c0 * SEQ + sx1]       = tf32_rna(a4[2] + bx);
                p1[(size_t)(c0 + 1) * SEQ + sx1] = tf32_rna(a4[3] + by);
            } else if (EPI == 3) {
                const int p0 = permk(c0), p1 = permk(c0 + 1);
                Cz[(size_t)r0 * ldc + p0]       = tf32_rna(a4[0]);
                Cz[(size_t)r0 * ldc + p1]       = tf32_rna(a4[1]);
                Cz[(size_t)(r0 + 8) * ldc + p0] = tf32_rna(a4[2]);
                Cz[(size_t)(r0 + 8) * ldc + p1] = tf32_rna(a4[3]);
            } else {
                const float bx = bias[c0], by = bias[c0 + 1];
                const float2 rs0 = *reinterpret_cast<const float2*>(
                    &resid[(size_t)r0 * ldc + c0]);
                const float2 rs1 = *reinterpret_cast<const float2*>(
                    &resid[(size_t)(r0 + 8) * ldc + c0]);
                float2 v0, v1;
                v0.x = a4[0] + bx + rs0.x; v0.y = a4[1] + by + rs0.y;
                v1.x = a4[2] + bx + rs1.x; v1.y = a4[3] + by + rs1.y;
                *reinterpret_cast<float2*>(&Cz[(size_t)r0 * ldc + c0]) = v0;
                *reinterpret_cast<float2*>(&Cz[(size_t)(r0 + 8) * ldc + c0]) = v1;
            }
        }
    }
}

// ---------------- prep: fused fp32 -> bf16 hi/lo [+ tf32 for kv] -----------
__global__ void split_all(const float4* __restrict__ q, const float4* __restrict__ kv,
                          __nv_bfloat16* __restrict__ dh,
                          __nv_bfloat16* __restrict__ dl,
                          float* __restrict__ kv32, int n4)
{
    int id = blockIdx.x * 256 + threadIdx.x;
    if (id >= 2 * n4) return;
    const bool is_kv = (id >= n4);
    const float4 v = is_kv ? kv[id - n4] : q[id];
    const int e0 = id * 4;
    const int base = e0 & ~511;
    const float vv[4] = {v.x, v.y, v.z, v.w};
#pragma unroll
    for (int u = 0; u < 4; u++) {
        const int k = (e0 + u) & 511;
        const float x = vv[u];
        const __nv_bfloat16 h = __float2bfloat16(x);
        const int pb = permkb(k);
        dh[base + pb] = h;
        dl[base + pb] = __float2bfloat16(x - __bfloat162float(h));
        if (is_kv) kv32[(base - (int)BND) + permk(k)] = tf32_rna(x);
    }
}

// ---------------- prep: weight transposes ----------------------------------
__global__ void wprep_all(const float* __restrict__ Wq, const float* __restrict__ Wk,
                          const float* __restrict__ Wv, const float* __restrict__ Wo,
                          __nv_bfloat16* __restrict__ wbh,
                          __nv_bfloat16* __restrict__ wbl,
                          float* __restrict__ vh, float* __restrict__ oh)
{
    const int idx = blockIdx.x * 256 + threadIdx.x;
    const int wsel = blockIdx.y;
    const int n = idx & 511;
    const int k = idx >> 9;
    if (wsel < 2) {
        const float w = (wsel ? Wk : Wq)[(size_t)k * DIM + n];
        const __nv_bfloat16 h = __float2bfloat16(w);
        const size_t dst = (size_t)wsel * DIM * DIM + (size_t)n * DIM + permkb(k);
        wbh[dst] = h;
        wbl[dst] = __float2bfloat16(w - __bfloat162float(h));
    } else {
        const float w = (wsel == 2 ? Wv : Wo)[(size_t)k * DIM + n];
        float* T = (wsel == 2) ? vh : oh;
        T[(size_t)n * DIM + permk(k)] = tf32_rna(w);
    }
}

// ---------------- softmax (rows of 2048), output tf32-rounded --------------
__global__ void __launch_bounds__(256) softmax_rows(float* __restrict__ S)
{
    const size_t row = blockIdx.x;
    float* p = S + row * (size_t)SEQ;
    const int t = threadIdx.x;
    float vals[8];
    float m = -3.402823466e38f;
#pragma unroll
    for (int i = 0; i < 8; i++) { vals[i] = p[t + i * 256]; m = fmaxf(m, vals[i]); }
    __shared__ float red[256];
    red[t] = m; __syncthreads();
#pragma unroll
    for (int s = 128; s > 0; s >>= 1) { if (t < s) red[t] = fmaxf(red[t], red[t+s]); __syncthreads(); }
    m = red[0]; __syncthreads();
    float sum = 0.0f;
#pragma unroll
    for (int i = 0; i < 8; i++) { vals[i] = __expf(vals[i] - m); sum += vals[i]; }
    red[t] = sum; __syncthreads();
#pragma unroll
    for (int s = 128; s > 0; s >>= 1) { if (t < s) red[t] += red[t+s]; __syncthreads(); }
    const float inv = 1.0f / red[0];
#pragma unroll
    for (int i = 0; i < 8; i++) p[t + i * 256] = tf32_rna(vals[i] * inv);
}

// ---------------- launcher --------------------------------------------------
extern "C" void kernel_launch(void* const* d_in, const int* in_sizes, int n_in,
                              void* d_out, int out_size)
{
    (void)in_sizes; (void)n_in; (void)out_size;
    const float* query     = (const float*)d_in[0];
    const float* key_value = (const float*)d_in[1];
    const float* Wq = (const float*)d_in[2];
    const float* bq = (const float*)d_in[3];
    const float* Wk = (const float*)d_in[4];
    const float* bk = (const float*)d_in[5];
    const float* Wv = (const float*)d_in[6];
    const float* bv = (const float*)d_in[7];
    const float* Wo = (const float*)d_in[8];
    const float* bo = (const float*)d_in[9];
    float* out = (float*)d_out;

    __nv_bfloat16 *in_bh, *in_bl, *qk_bh, *qk_bl, *wbh, *wbl;
    float *kv_t32, *vt, *s, *o, *wvt, *wot;
    cudaGetSymbolAddress((void**)&in_bh,  g_in_bh);
    cudaGetSymbolAddress((void**)&in_bl,  g_in_bl);
    cudaGetSymbolAddress((void**)&kv_t32, g_kv_t32);
    cudaGetSymbolAddress((void**)&qk_bh,  g_qk_bh);
    cudaGetSymbolAddress((void**)&qk_bl,  g_qk_bl);
    cudaGetSymbolAddress((void**)&vt,     g_vt);
    cudaGetSymbolAddress((void**)&s,      g_s);
    cudaGetSymbolAddress((void**)&o,      g_o);
    cudaGetSymbolAddress((void**)&wbh,    g_wqk_bh);
    cudaGetSymbolAddress((void**)&wbl,    g_wqk_bl);
    cudaGetSymbolAddress((void**)&wvt,    g_wvt);
    cudaGetSymbolAddress((void**)&wot,    g_wot);

    constexpr int SMB = 2 * 2 * 128 * 160;   // 81920 B
    constexpr int SM1 = 2 * 2 * TILE_B;      // 81920 B
    cudaFuncSetAttribute(gemm_bf16<0>, cudaFuncAttributeMaxDynamicSharedMemorySize, SMB);
    cudaFuncSetAttribute(gemm_bf16<2>, cudaFuncAttributeMaxDynamicSharedMemorySize, SMB);
    cudaFuncSetAttribute(gemm_t32<1>, cudaFuncAttributeMaxDynamicSharedMemorySize, SM1);
    cudaFuncSetAttribute(gemm_t32<3>, cudaFuncAttributeMaxDynamicSharedMemorySize, SM1);
    cudaFuncSetAttribute(gemm_t32<4>, cudaFuncAttributeMaxDynamicSharedMemorySize, SM1);

    const size_t sQKV = (size_t)SEQ * DIM;
    const size_t sS   = (size_t)SEQ * SEQ;
    const size_t sVT  = (size_t)DIM * SEQ;
    const int n4 = (int)(BND / 4);

    // 0: fused input splits (query + key_value, kv also -> tf32)
    split_all<<<(2 * n4) / 256, 256>>>((const float4*)query,
        (const float4*)key_value, in_bh, in_bl, kv_t32, n4);
    // 1: weight transposes
    {
        dim3 g((DIM * DIM) / 256, 4);
        wprep_all<<<g, 256>>>(Wq, Wk, Wv, Wo, wbh, wbl, wvt, wot);
    }
    // 2: v projection -> transposed VT (tf32 1-pass)
    {
        dim3 grid(DIM / 128, (BB * SEQ) / 128, 1);
        gemm_t32<1><<<grid, 256, SM1>>>(kv_t32, wvt, vt, bv, nullptr,
                                        DIM, DIM, DIM, 0, 0, 0, 0);
    }
    // 3: q,k projections fused (bf16x3, z = projection)
    {
        dim3 grid(DIM / 128, (BB * SEQ) / 128, 2);
        gemm_bf16<0><<<grid, 512, SMB>>>(in_bh, in_bl, wbh, wbl,
            qk_bh, qk_bl, bq, bk, DIM, DIM, DIM, DIM,
            BND, (size_t)DIM * DIM, BND, 1.0f);
    }
    // 4: S = sqrt(512) * q @ k^T (bf16x3, batched)
    {
        dim3 grid(SEQ / 128, SEQ / 128, BB);
        gemm_bf16<2><<<grid, 512, SMB>>>(qk_bh, qk_bl, qk_bh + BND, qk_bl + BND,
            s, nullptr, nullptr, nullptr, DIM, DIM, DIM, SEQ,
            sQKV, sQKV, sS, SCALE_F);
    }
    // 5: softmax
    softmax_rows<<<BB * SEQ, 256>>>(s);
    // 6: O = P @ V (tf32 1-pass, batched)
    {
        dim3 grid(DIM / 128, SEQ / 128, BB);
        gemm_t32<3><<<grid, 256, SM1>>>(s, vt, o, nullptr, nullptr,
                                        SEQ, SEQ, SEQ, DIM, sS, sVT, sQKV);
    }
    // 7: out = query + O @ Wo + bo (tf32 1-pass)
    {
        dim3 grid(DIM / 128, (BB * SEQ) / 128, 1);
        gemm_t32<4><<<grid, 256, SM1>>>(o, wot, out, bo, query,
                                        DIM, DIM, DIM, DIM, 0, 0, 0);
    }
}

// round 11
// speedup vs baseline: 1.5909x; 1.0599x over previous
#include <cuda_runtime.h>
#include <cuda_bf16.h>
#include <cuda_fp16.h>
#include <cstdint>

// ===========================================================================
// AxisAttention: bf16x3 (m16n8k16) for q/k projections + QK^T (hh+hl+lh);
// fp16 single-pass (m16n8k16) for PV; tf32 single-pass for v-proj, out-proj.
// Proj epilogue staged through smem for coalesced bf16 stores.
// B=4, N=2048, D=DA=512.
// ===========================================================================

constexpr int BB  = 4;
constexpr int SEQ = 2048;
constexpr int DIM = 512;
constexpr float SCALE_F = 22.62741699796952f;  // sqrt(512), multiplied

constexpr size_t BND = (size_t)BB * SEQ * DIM;

// ---------------- device global scratch -------------------------------------
__device__ __nv_bfloat16 g_in_bh[2 * BND];
__device__ __nv_bfloat16 g_in_bl[2 * BND];
__device__ float         g_kv_t32[BND];
__device__ __nv_bfloat16 g_qk_bh[2 * BND];
__device__ __nv_bfloat16 g_qk_bl[2 * BND];
__device__ __half g_vt[(size_t)BB * DIM * SEQ];      // V^T fp16 [DIM, SEQ]
__device__ float  g_s[(size_t)BB * SEQ * SEQ];       // scores fp32
__device__ __half g_pf[(size_t)BB * SEQ * SEQ];      // probs fp16
__device__ float  g_o[BND];
__device__ __nv_bfloat16 g_wqk_bh[2 * DIM * DIM];
__device__ __nv_bfloat16 g_wqk_bl[2 * DIM * DIM];
__device__ float g_wvt[DIM * DIM];
__device__ float g_wot[DIM * DIM];

// ---------------- helpers ----------------------------------------------------
__device__ __forceinline__ uint32_t smem_u32(const void* p) {
    uint32_t a;
    asm("{ .reg .u64 t; cvta.to.shared.u64 t, %1; cvt.u32.u64 %0, t; }"
        : "=r"(a) : "l"(p));
    return a;
}
__device__ __forceinline__ float tf32_rna(float x) {
    uint32_t u;
    asm("cvt.rna.tf32.f32 %0, %1;" : "=r"(u) : "f"(x));
    return __uint_as_float(u);
}
__device__ __forceinline__ void cp16(uint32_t saddr, const void* g) {
    asm volatile("cp.async.cg.shared.global [%0], [%1], 16;"
                 :: "r"(saddr), "l"(g) : "memory");
}
__device__ __forceinline__ void cp_commit() {
    asm volatile("cp.async.commit_group;" ::: "memory");
}
template <int N>
__device__ __forceinline__ void cp_wait() {
    asm volatile("cp.async.wait_group %0;" :: "n"(N) : "memory");
}

// tf32 perm within 16
__device__ __forceinline__ int permk(int k) {
    const int lo = k & 7;
    return (k & ~15) | ((k & 8) + 2 * (lo & 3) + (lo >> 2));
}
// 16-bit-mma perm within 16: logical 8e+2q+d -> phys 4q+2e+d
__device__ __forceinline__ int permkb(int k) {
    const int t = k & 15;
    const int q = (t & 7) >> 1, d = t & 1, e = t >> 3;
    return (k & ~15) | (4 * q + 2 * e + d);
}

// mma.sync m16n8k8 tf32
__device__ __forceinline__ void mma8(float* c, float a0, float a1, float a2,
                                     float a3, float b0, float b1) {
    asm volatile(
        "mma.sync.aligned.m16n8k8.row.col.f32.tf32.tf32.f32 "
        "{%0,%1,%2,%3}, {%4,%5,%6,%7}, {%8,%9}, {%0,%1,%2,%3};"
        : "+f"(c[0]), "+f"(c[1]), "+f"(c[2]), "+f"(c[3])
        : "r"(__float_as_uint(a0)), "r"(__float_as_uint(a1)),
          "r"(__float_as_uint(a2)), "r"(__float_as_uint(a3)),
          "r"(__float_as_uint(b0)), "r"(__float_as_uint(b1)));
}
// mma.sync m16n8k16 bf16
__device__ __forceinline__ void mma16(float* c, uint32_t a0, uint32_t a1,
                                      uint32_t a2, uint32_t a3,
                                      uint32_t b0, uint32_t b1) {
    asm volatile(
        "mma.sync.aligned.m16n8k16.row.col.f32.bf16.bf16.f32 "
        "{%0,%1,%2,%3}, {%4,%5,%6,%7}, {%8,%9}, {%0,%1,%2,%3};"
        : "+f"(c[0]), "+f"(c[1]), "+f"(c[2]), "+f"(c[3])
        : "r"(a0), "r"(a1), "r"(a2), "r"(a3), "r"(b0), "r"(b1));
}
// mma.sync m16n8k16 fp16
__device__ __forceinline__ void mma16h(float* c, uint32_t a0, uint32_t a1,
                                       uint32_t a2, uint32_t a3,
                                       uint32_t b0, uint32_t b1) {
    asm volatile(
        "mma.sync.aligned.m16n8k16.row.col.f32.f16.f16.f32 "
        "{%0,%1,%2,%3}, {%4,%5,%6,%7}, {%8,%9}, {%0,%1,%2,%3};"
        : "+f"(c[0]), "+f"(c[1]), "+f"(c[2]), "+f"(c[3])
        : "r"(a0), "r"(a1), "r"(a2), "r"(a3), "r"(b0), "r"(b1));
}
__device__ __forceinline__ uint32_t f2u(float x) { return __float_as_uint(x); }

// ===========================================================================
// bf16 split GEMM (hh+hl+lh): CTA 128x128, 512 thr, 4x4 warps, warp 32x32,
// K-chunk 32, double buffer. SMEM row: [hi 64B | lo 64B | pad 32B] = 160B.
// EPI 0: bf16 hi/lo split out via smem staging (coalesced).
// EPI 2: alpha-scaled fp32 out, permkb cols (scores for softmax/PV-fp16).
// ===========================================================================
template <int EPI>
__global__ void __launch_bounds__(512, 1) gemm_bf16(
    const __nv_bfloat16* __restrict__ Ahi, const __nv_bfloat16* __restrict__ Alo,
    const __nv_bfloat16* __restrict__ Bhi, const __nv_bfloat16* __restrict__ Blo,
    void* __restrict__ Cp, void* __restrict__ C2p,
    const float* __restrict__ bias, const float* __restrict__ bias2,
    int K, int lda, int ldb, int ldc,
    size_t sA, size_t sB, size_t sC, float alpha)
{
    constexpr int IT = 2, WN = 4;
    constexpr int ROWB  = 160;
    constexpr int TILEB = 128 * ROWB;
    constexpr int STAGEB = 2 * TILEB;

    extern __shared__ char smc[];
    const uint32_t sb = smem_u32(smc);

    const int tid    = threadIdx.x;
    const int lane   = tid & 31;
    const int wid    = tid >> 5;
    const int warp_m = wid >> 2;
    const int warp_n = wid & 3;
    const int q      = lane & 3;
    const int n0 = blockIdx.x * 128;
    const int m0 = blockIdx.y * 128;
    const int z  = blockIdx.z;

    const float* bias_z = (EPI == 0 && z == 1) ? bias2 : bias;

    const __nv_bfloat16* A0 = Ahi + (size_t)z * sA + (size_t)m0 * lda;
    const __nv_bfloat16* A1 = Alo + (size_t)z * sA + (size_t)m0 * lda;
    const __nv_bfloat16* B0 = Bhi + (size_t)z * sB + (size_t)n0 * ldb;
    const __nv_bfloat16* B1 = Blo + (size_t)z * sB + (size_t)n0 * ldb;

    float acc[IT][WN][4];
#pragma unroll
    for (int i = 0; i < IT; i++)
#pragma unroll
        for (int j = 0; j < WN; j++)
#pragma unroll
            for (int l = 0; l < 4; l++) acc[i][j][l] = 0.0f;

    const int nch = K / 32;

    auto load_stage = [&](int buf, int c) {
        const uint32_t st = sb + (uint32_t)buf * STAGEB;
#pragma unroll
        for (int i = 0; i < 4; i++) {
            const int idx = tid + i * 512;
            const int tile = idx >> 10;
            const int w    = idx & 1023;
            const int row  = w >> 3;
            const int h    = (w >> 2) & 1;
            const int cc   = w & 3;
            const __nv_bfloat16* src =
                tile ? (h ? B1 : B0) : (h ? A1 : A0);
            const int ld = tile ? ldb : lda;
            cp16(st + (uint32_t)(tile * TILEB + row * ROWB + h * 64 + cc * 16),
                 src + (size_t)row * ld + c * 32 + cc * 8);
        }
    };

    load_stage(0, 0);
    cp_commit();

    const int arow0 = warp_m * 32 + (lane >> 2);
    const int bcol0 = warp_n * 32 + (lane >> 2);

    for (int c = 0; c < nch; c++) {
        if (c + 1 < nch) {
            load_stage((c + 1) & 1, c + 1);
            cp_commit();
            cp_wait<1>();
        } else {
            cp_wait<0>();
        }
        __syncthreads();

        const char* stg = smc + (size_t)(c & 1) * STAGEB;
        const char* Ab  = stg;
        const char* Bb  = stg + TILEB;

#pragma unroll
        for (int b = 0; b < 2; b++) {
            const int kb = b * 32 + 8 * q;
            float2 Ah0[IT], Ah1[IT], Al0[IT], Al1[IT];
#pragma unroll
            for (int i = 0; i < IT; i++) {
                const int row = arow0 + i * 16;
                Ah0[i] = *reinterpret_cast<const float2*>(Ab + row * ROWB + kb);
                Ah1[i] = *reinterpret_cast<const float2*>(Ab + (row + 8) * ROWB + kb);
                Al0[i] = *reinterpret_cast<const float2*>(Ab + row * ROWB + 64 + kb);
                Al1[i] = *reinterpret_cast<const float2*>(Ab + (row + 8) * ROWB + 64 + kb);
            }
            float2 Bh[WN], Bl[WN];
#pragma unroll
            for (int j = 0; j < WN; j++) {
                const int col = bcol0 + j * 8;
                Bh[j] = *reinterpret_cast<const float2*>(Bb + col * ROWB + kb);
                Bl[j] = *reinterpret_cast<const float2*>(Bb + col * ROWB + 64 + kb);
            }
#pragma unroll
            for (int i = 0; i < IT; i++)
#pragma unroll
                for (int j = 0; j < WN; j++)
                    mma16(acc[i][j], f2u(Ah0[i].x), f2u(Ah1[i].x),
                          f2u(Ah0[i].y), f2u(Ah1[i].y), f2u(Bh[j].x), f2u(Bh[j].y));
#pragma unroll
            for (int i = 0; i < IT; i++)
#pragma unroll
                for (int j = 0; j < WN; j++)
                    mma16(acc[i][j], f2u(Ah0[i].x), f2u(Ah1[i].x),
                          f2u(Ah0[i].y), f2u(Ah1[i].y), f2u(Bl[j].x), f2u(Bl[j].y));
#pragma unroll
            for (int i = 0; i < IT; i++)
#pragma unroll
                for (int j = 0; j < WN; j++)
                    mma16(acc[i][j], f2u(Al0[i].x), f2u(Al1[i].x),
                          f2u(Al0[i].y), f2u(Al1[i].y), f2u(Bh[j].x), f2u(Bh[j].y));
        }
        __syncthreads();
    }

    // ---------------- epilogue ----------------
    if (EPI == 0) {
        // stage bf16 hi/lo tiles in smem, then coalesced copy out
        __nv_bfloat16* sh = reinterpret_cast<__nv_bfloat16*>(smc);
        __nv_bfloat16* sl = sh + 128 * 128;
#pragma unroll
        for (int i = 0; i < IT; i++) {
#pragma unroll
            for (int j = 0; j < WN; j++) {
                const float* a4 = acc[i][j];
                const int lr = warp_m * 32 + i * 16 + (lane >> 2);
                const int lc = warp_n * 32 + j * 8 + 2 * q;
                const float bx = bias_z[n0 + lc], by = bias_z[n0 + lc + 1];
                const int p0 = permkb(lc), p1 = permkb(lc + 1);
                const float v[4] = {a4[0] + bx, a4[1] + by, a4[2] + bx, a4[3] + by};
                const int rr[4] = {lr, lr, lr + 8, lr + 8};
                const int pp[4] = {p0, p1, p0, p1};
#pragma unroll
                for (int u = 0; u < 4; u++) {
                    const __nv_bfloat16 h = __float2bfloat16(v[u]);
                    sh[rr[u] * 128 + pp[u]] = h;
                    sl[rr[u] * 128 + pp[u]] =
                        __float2bfloat16(v[u] - __bfloat162float(h));
                }
            }
        }
        __syncthreads();
        __nv_bfloat16* Cz  = (__nv_bfloat16*)Cp  + (size_t)z * sC;
        __nv_bfloat16* C2z = (__nv_bfloat16*)C2p + (size_t)z * sC;
#pragma unroll
        for (int t = 0; t < 4; t++) {
            const int idx = tid + t * 512;         // 0..2047
            const int row = idx >> 4;
            const int c16 = idx & 15;
            *reinterpret_cast<uint4*>(Cz + (size_t)(m0 + row) * ldc + n0 + c16 * 8) =
                *reinterpret_cast<const uint4*>(sh + row * 128 + c16 * 8);
            *reinterpret_cast<uint4*>(C2z + (size_t)(m0 + row) * ldc + n0 + c16 * 8) =
                *reinterpret_cast<const uint4*>(sl + row * 128 + c16 * 8);
        }
    } else {
        float* Cz = (float*)Cp + (size_t)z * sC;
#pragma unroll
        for (int i = 0; i < IT; i++) {
#pragma unroll
            for (int j = 0; j < WN; j++) {
                const float* a4 = acc[i][j];
                const int r0 = m0 + warp_m * 32 + i * 16 + (lane >> 2);
                const int c0 = n0 + warp_n * 32 + j * 8 + 2 * q;
                const int p0 = permkb(c0), p1 = permkb(c0 + 1);
                Cz[(size_t)r0 * ldc + p0]       = alpha * a4[0];
                Cz[(size_t)r0 * ldc + p1]       = alpha * a4[1];
                Cz[(size_t)(r0 + 8) * ldc + p0] = alpha * a4[2];
                Cz[(size_t)(r0 + 8) * ldc + p1] = alpha * a4[3];
            }
        }
    }
}

// ===========================================================================
// fp16 single-pass GEMM (PV): CTA 128x128, 256 thr occ 2, warp 64x32 (IT=4),
// K-chunk 32, ROWB=80. Output: fp32, tf32-rounded, permk cols.
// ===========================================================================
__global__ void __launch_bounds__(256, 2) gemm_f16(
    const __half* __restrict__ A, const __half* __restrict__ B,
    float* __restrict__ C,
    int K, int lda, int ldb, int ldc,
    size_t sA, size_t sB, size_t sC)
{
    constexpr int IT = 4;
    constexpr int ROWB  = 80;
    constexpr int TILEB = 128 * ROWB;     // 10240
    constexpr int STAGEB = 2 * TILEB;     // 20480

    extern __shared__ char smc[];
    const uint32_t sb = smem_u32(smc);

    const int tid    = threadIdx.x;
    const int lane   = tid & 31;
    const int wid    = tid >> 5;
    const int warp_m = wid >> 2;
    const int warp_n = wid & 3;
    const int q      = lane & 3;
    const int n0 = blockIdx.x * 128;
    const int m0 = blockIdx.y * 128;
    const int z  = blockIdx.z;

    const __half* A0 = A + (size_t)z * sA + (size_t)m0 * lda;
    const __half* B0 = B + (size_t)z * sB + (size_t)n0 * ldb;

    float acc[IT][4][4];
#pragma unroll
    for (int i = 0; i < IT; i++)
#pragma unroll
        for (int j = 0; j < 4; j++)
#pragma unroll
            for (int l = 0; l < 4; l++) acc[i][j][l] = 0.0f;

    const int nch = K / 32;

    auto load_stage = [&](int buf, int c) {
        const uint32_t st = sb + (uint32_t)buf * STAGEB;
#pragma unroll
        for (int i = 0; i < 4; i++) {
            const int idx = tid + i * 256;          // 0..1023
            const int tile = idx >> 9;
            const int w    = idx & 511;
            const int row  = w >> 2;
            const int cc   = w & 3;
            const __half* src = tile ? B0 : A0;
            const int ld = tile ? ldb : lda;
            cp16(st + (uint32_t)(tile * TILEB + row * ROWB + cc * 16),
                 src + (size_t)row * ld + c * 32 + cc * 8);
        }
    };

    load_stage(0, 0);
    cp_commit();

    const int arow0 = warp_m * 64 + (lane >> 2);
    const int bcol0 = warp_n * 32 + (lane >> 2);

    for (int c = 0; c < nch; c++) {
        if (c + 1 < nch) {
            load_stage((c + 1) & 1, c + 1);
            cp_commit();
            cp_wait<1>();
        } else {
            cp_wait<0>();
        }
        __syncthreads();

        const char* stg = smc + (size_t)(c & 1) * STAGEB;
        const char* Ab  = stg;
        const char* Bb  = stg + TILEB;

#pragma unroll
        for (int b = 0; b < 2; b++) {
            const int kb = b * 32 + 8 * q;
            float2 a0[IT], a1[IT], b0[4];
#pragma unroll
            for (int i = 0; i < IT; i++) {
                const int row = arow0 + i * 16;
                a0[i] = *reinterpret_cast<const float2*>(Ab + row * ROWB + kb);
                a1[i] = *reinterpret_cast<const float2*>(Ab + (row + 8) * ROWB + kb);
            }
#pragma unroll
            for (int j = 0; j < 4; j++)
                b0[j] = *reinterpret_cast<const float2*>(
                    Bb + (bcol0 + j * 8) * ROWB + kb);
#pragma unroll
            for (int i = 0; i < IT; i++)
#pragma unroll
                for (int j = 0; j < 4; j++)
                    mma16h(acc[i][j], f2u(a0[i].x), f2u(a1[i].x),
                           f2u(a0[i].y), f2u(a1[i].y), f2u(b0[j].x), f2u(b0[j].y));
        }
        __syncthreads();
    }

    float* Cz = C + (size_t)z * sC;
#pragma unroll
    for (int i = 0; i < IT; i++) {
#pragma unroll
        for (int j = 0; j < 4; j++) {
            const float* a4 = acc[i][j];
            const int r0 = m0 + warp_m * 64 + i * 16 + (lane >> 2);
            const int c0 = n0 + warp_n * 32 + j * 8 + 2 * q;
            const int p0 = permk(c0), p1 = permk(c0 + 1);
            Cz[(size_t)r0 * ldc + p0]       = tf32_rna(a4[0]);
            Cz[(size_t)r0 * ldc + p1]       = tf32_rna(a4[1]);
            Cz[(size_t)(r0 + 8) * ldc + p0] = tf32_rna(a4[2]);
            Cz[(size_t)(r0 + 8) * ldc + p1] = tf32_rna(a4[3]);
        }
    }
}

// ===========================================================================
// tf32 1-pass GEMM: CTA 128x128, 256 thr occ 2, warp 64x32, K-chunk 32.
// EPI: 1=transposed fp16 VT+bias (permkb seq), 4=bias+residual fp32.
// ===========================================================================
constexpr int LDW    = 40;
constexpr int TILE_F = 128 * LDW;
constexpr int TILE_B = TILE_F * 4;

__device__ __forceinline__ void load_tile32(
    uint32_t sbase, const float* __restrict__ g, int ld, int tid)
{
#pragma unroll
    for (int i = 0; i < 4; i++) {
        const int f  = tid + i * 256;
        const int r  = f >> 3;
        const int c4 = (f & 7) << 2;
        cp16(sbase + (uint32_t)(r * LDW + c4) * 4, g + (size_t)r * ld + c4);
    }
}

template <int EPI>
__global__ void __launch_bounds__(256, 2) gemm_t32(
    const float* __restrict__ A, const float* __restrict__ B,
    float* __restrict__ C,
    const float* __restrict__ bias, const float* __restrict__ resid,
    int K, int lda, int ldb, int ldc,
    size_t sA, size_t sB, size_t sC)
{
    constexpr int IT = 4;
    extern __shared__ float smf[];
    const uint32_t sb = smem_u32(smf);

    const int tid    = threadIdx.x;
    const int lane   = tid & 31;
    const int wid    = tid >> 5;
    const int warp_m = wid >> 2;
    const int warp_n = wid & 3;
    const int n0 = blockIdx.x * 128;
    const int m0 = blockIdx.y * 128;
    const int z  = blockIdx.z;

    const float* A0 = A + (size_t)z * sA + (size_t)m0 * lda;
    const float* B0 = B + (size_t)z * sB + (size_t)n0 * ldb;

    float acc[IT][4][4];
#pragma unroll
    for (int i = 0; i < IT; i++)
#pragma unroll
        for (int j = 0; j < 4; j++)
#pragma unroll
            for (int l = 0; l < 4; l++) acc[i][j][l] = 0.0f;

    const int nch = K / 32;

    auto load_stage = [&](int buf, int c) {
        const uint32_t st = sb + (uint32_t)buf * 2 * TILE_B;
        load_tile32(st,          A0 + c * 32, lda, tid);
        load_tile32(st + TILE_B, B0 + c * 32, ldb, tid);
    };

    load_stage(0, 0);
    cp_commit();

    const int arow0 = warp_m * 64 + (lane >> 2);
    const int bcol0 = warp_n * 32 + (lane >> 2);
    const int kq2   = 2 * (lane & 3);

    for (int c = 0; c < nch; c++) {
        if (c + 1 < nch) {
            load_stage((c + 1) & 1, c + 1);
            cp_commit();
            cp_wait<1>();
        } else {
            cp_wait<0>();
        }
        __syncthreads();

        const float* st  = smf + (size_t)(c & 1) * 2 * TILE_F;
        const float* Ath = st;
        const float* Bth = st + TILE_F;

#pragma unroll
        for (int s = 0; s < 4; s++) {
            const int ko = s * 8 + kq2;
            float2 a0[IT], a1[IT], b0[4];
#pragma unroll
            for (int i = 0; i < IT; i++) {
                a0[i] = *reinterpret_cast<const float2*>(
                    Ath + (size_t)(arow0 + i * 16) * LDW + ko);
                a1[i] = *reinterpret_cast<const float2*>(
                    Ath + (size_t)(arow0 + i * 16 + 8) * LDW + ko);
            }
#pragma unroll
            for (int j = 0; j < 4; j++)
                b0[j] = *reinterpret_cast<const float2*>(
                    Bth + (size_t)(bcol0 + j * 8) * LDW + ko);
#pragma unroll
            for (int i = 0; i < IT; i++)
#pragma unroll
                for (int j = 0; j < 4; j++)
                    mma8(acc[i][j], a0[i].x, a1[i].x, a0[i].y, a1[i].y,
                         b0[j].x, b0[j].y);
        }
        __syncthreads();
    }

    float* Cz = C + (size_t)z * sC;
#pragma unroll
    for (int i = 0; i < IT; i++) {
#pragma unroll
        for (int j = 0; j < 4; j++) {
            const float* a4 = acc[i][j];
            const int r0 = m0 + warp_m * 64 + i * 16 + (lane >> 2);
            const int c0 = n0 + warp_n * 32 + j * 8 + 2 * (lane & 3);
            if (EPI == 1) {            // transposed fp16 VT[b][dim][seq], permkb
                __half* Cv = (__half*)C;
                const float bx = bias[c0], by = bias[c0 + 1];
                const int b0i = r0 >> 11,        sx0 = permkb(r0 & (SEQ - 1));
                const int b1i = (r0 + 8) >> 11,  sx1 = permkb((r0 + 8) & (SEQ - 1));
                __half* p0 = Cv + (size_t)b0i * DIM * SEQ;
                __half* p1 = Cv + (size_t)b1i * DIM * SEQ;
                p0[(size_t)c0 * SEQ + sx0]       = __float2half(a4[0] + bx);
                p0[(size_t)(c0 + 1) * SEQ + sx0] = __float2half(a4[1] + by);
                p1[(size_t)c0 * SEQ + sx1]       = __float2half(a4[2] + bx);
                p1[(size_t)(c0 + 1) * SEQ + sx1] = __float2half(a4[3] + by);
            } else {                   // bias + residual (final out)
                const float bx = bias[c0], by = bias[c0 + 1];
                const float2 rs0 = *reinterpret_cast<const float2*>(
                    &resid[(size_t)r0 * ldc + c0]);
                const float2 rs1 = *reinterpret_cast<const float2*>(
                    &resid[(size_t)(r0 + 8) * ldc + c0]);
                float2 v0, v1;
                v0.x = a4[0] + bx + rs0.x; v0.y = a4[1] + by + rs0.y;
                v1.x = a4[2] + bx + rs1.x; v1.y = a4[3] + by + rs1.y;
                *reinterpret_cast<float2*>(&Cz[(size_t)r0 * ldc + c0]) = v0;
                *reinterpret_cast<float2*>(&Cz[(size_t)(r0 + 8) * ldc + c0]) = v1;
            }
        }
    }
}

// ---------------- prep: fused fp32 -> bf16 hi/lo [+ tf32 for kv] -----------
__global__ void split_all(const float4* __restrict__ q, const float4* __restrict__ kv,
                          __nv_bfloat16* __restrict__ dh,
                          __nv_bfloat16* __restrict__ dl,
                          float* __restrict__ kv32, int n4)
{
    int id = blockIdx.x * 256 + threadIdx.x;
    if (id >= 2 * n4) return;
    const bool is_kv = (id >= n4);
    const float4 v = is_kv ? kv[id - n4] : q[id];
    const int e0 = id * 4;
    const int base = e0 & ~511;
    const float vv[4] = {v.x, v.y, v.z, v.w};
#pragma unroll
    for (int u = 0; u < 4; u++) {
        const int k = (e0 + u) & 511;
        const float x = vv[u];
        const __nv_bfloat16 h = __float2bfloat16(x);
        const int pb = permkb(k);
        dh[base + pb] = h;
        dl[base + pb] = __float2bfloat16(x - __bfloat162float(h));
        if (is_kv) kv32[(base - (int)BND) + permk(k)] = tf32_rna(x);
    }
}

// ---------------- prep: weight transposes ----------------------------------
__global__ void wprep_all(const float* __restrict__ Wq, const float* __restrict__ Wk,
                          const float* __restrict__ Wv, const float* __restrict__ Wo,
                          __nv_bfloat16* __restrict__ wbh,
                          __nv_bfloat16* __restrict__ wbl,
                          float* __restrict__ vh, float* __restrict__ oh)
{
    const int idx = blockIdx.x * 256 + threadIdx.x;
    const int wsel = blockIdx.y;
    const int n = idx & 511;
    const int k = idx >> 9;
    if (wsel < 2) {
        const float w = (wsel ? Wk : Wq)[(size_t)k * DIM + n];
        const __nv_bfloat16 h = __float2bfloat16(w);
        const size_t dst = (size_t)wsel * DIM * DIM + (size_t)n * DIM + permkb(k);
        wbh[dst] = h;
        wbl[dst] = __float2bfloat16(w - __bfloat162float(h));
    } else {
        const float w = (wsel == 2 ? Wv : Wo)[(size_t)k * DIM + n];
        float* T = (wsel == 2) ? vh : oh;
        T[(size_t)n * DIM + permk(k)] = tf32_rna(w);
    }
}

// ---------------- softmax: read fp32 S, write fp16 P -----------------------
__global__ void __launch_bounds__(256) softmax_rows(const float* __restrict__ S,
                                                    __half* __restrict__ P)
{
    const size_t row = blockIdx.x;
    const float* p = S + row * (size_t)SEQ;
    __half* po = P + row * (size_t)SEQ;
    const int t = threadIdx.x;
    float vals[8];
    float m = -3.402823466e38f;
#pragma unroll
    for (int i = 0; i < 8; i++) { vals[i] = p[t + i * 256]; m = fmaxf(m, vals[i]); }
    __shared__ float red[256];
    red[t] = m; __syncthreads();
#pragma unroll
    for (int s = 128; s > 0; s >>= 1) { if (t < s) red[t] = fmaxf(red[t], red[t+s]); __syncthreads(); }
    m = red[0]; __syncthreads();
    float sum = 0.0f;
#pragma unroll
    for (int i = 0; i < 8; i++) { vals[i] = __expf(vals[i] - m); sum += vals[i]; }
    red[t] = sum; __syncthreads();
#pragma unroll
    for (int s = 128; s > 0; s >>= 1) { if (t < s) red[t] += red[t+s]; __syncthreads(); }
    const float inv = 1.0f / red[0];
#pragma unroll
    for (int i = 0; i < 8; i++) po[t + i * 256] = __float2half(vals[i] * inv);
}

// ---------------- launcher --------------------------------------------------
extern "C" void kernel_launch(void* const* d_in, const int* in_sizes, int n_in,
                              void* d_out, int out_size)
{
    (void)in_sizes; (void)n_in; (void)out_size;
    const float* query     = (const float*)d_in[0];
    const float* key_value = (const float*)d_in[1];
    const float* Wq = (const float*)d_in[2];
    const float* bq = (const float*)d_in[3];
    const float* Wk = (const float*)d_in[4];
    const float* bk = (const float*)d_in[5];
    const float* Wv = (const float*)d_in[6];
    const float* bv = (const float*)d_in[7];
    const float* Wo = (const float*)d_in[8];
    const float* bo = (const float*)d_in[9];
    float* out = (float*)d_out;

    __nv_bfloat16 *in_bh, *in_bl, *qk_bh, *qk_bl, *wbh, *wbl;
    __half *vt, *pf;
    float *kv_t32, *s, *o, *wvt, *wot;
    cudaGetSymbolAddress((void**)&in_bh,  g_in_bh);
    cudaGetSymbolAddress((void**)&in_bl,  g_in_bl);
    cudaGetSymbolAddress((void**)&kv_t32, g_kv_t32);
    cudaGetSymbolAddress((void**)&qk_bh,  g_qk_bh);
    cudaGetSymbolAddress((void**)&qk_bl,  g_qk_bl);
    cudaGetSymbolAddress((void**)&vt,     g_vt);
    cudaGetSymbolAddress((void**)&s,      g_s);
    cudaGetSymbolAddress((void**)&pf,     g_pf);
    cudaGetSymbolAddress((void**)&o,      g_o);
    cudaGetSymbolAddress((void**)&wbh,    g_wqk_bh);
    cudaGetSymbolAddress((void**)&wbl,    g_wqk_bl);
    cudaGetSymbolAddress((void**)&wvt,    g_wvt);
    cudaGetSymbolAddress((void**)&wot,    g_wot);

    constexpr int SMB = 2 * 2 * 128 * 160;   // 81920 B (bf16 kernels)
    constexpr int SMH = 2 * 2 * 128 * 80;    // 40960 B (fp16 kernel)
    constexpr int SM1 = 2 * 2 * TILE_B;      // 81920 B (tf32 kernels)
    cudaFuncSetAttribute(gemm_bf16<0>, cudaFuncAttributeMaxDynamicSharedMemorySize, SMB);
    cudaFuncSetAttribute(gemm_bf16<2>, cudaFuncAttributeMaxDynamicSharedMemorySize, SMB);
    cudaFuncSetAttribute(gemm_f16, cudaFuncAttributeMaxDynamicSharedMemorySize, SMH);
    cudaFuncSetAttribute(gemm_t32<1>, cudaFuncAttributeMaxDynamicSharedMemorySize, SM1);
    cudaFuncSetAttribute(gemm_t32<4>, cudaFuncAttributeMaxDynamicSharedMemorySize, SM1);

    const size_t sQKV = (size_t)SEQ * DIM;
    const size_t sS   = (size_t)SEQ * SEQ;
    const size_t sVT  = (size_t)DIM * SEQ;
    const int n4 = (int)(BND / 4);

    // 0: fused input splits
    split_all<<<(2 * n4) / 256, 256>>>((const float4*)query,
        (const float4*)key_value, in_bh, in_bl, kv_t32, n4);
    // 1: weight transposes
    {
        dim3 g((DIM * DIM) / 256, 4);
        wprep_all<<<g, 256>>>(Wq, Wk, Wv, Wo, wbh, wbl, wvt, wot);
    }
    // 2: v projection -> transposed fp16 VT (tf32 1-pass)
    {
        dim3 grid(DIM / 128, (BB * SEQ) / 128, 1);
        gemm_t32<1><<<grid, 256, SM1>>>(kv_t32, wvt, (float*)vt, bv, nullptr,
                                        DIM, DIM, DIM, 0, 0, 0, 0);
    }
    // 3: q,k projections fused (bf16x3, staged epilogue)
    {
        dim3 grid(DIM / 128, (BB * SEQ) / 128, 2);
        gemm_bf16<0><<<grid, 512, SMB>>>(in_bh, in_bl, wbh, wbl,
            qk_bh, qk_bl, bq, bk, DIM, DIM, DIM, DIM,
            BND, (size_t)DIM * DIM, BND, 1.0f);
    }
    // 4: S = sqrt(512) * q @ k^T (bf16x3, batched, permkb cols)
    {
        dim3 grid(SEQ / 128, SEQ / 128, BB);
        gemm_bf16<2><<<grid, 512, SMB>>>(qk_bh, qk_bl, qk_bh + BND, qk_bl + BND,
            s, nullptr, nullptr, nullptr, DIM, DIM, DIM, SEQ,
            sQKV, sQKV, sS, SCALE_F);
    }
    // 5: softmax (fp32 -> fp16 P)
    softmax_rows<<<BB * SEQ, 256>>>(s, pf);
    // 6: O = P @ V (fp16 single-pass, batched)
    {
        dim3 grid(DIM / 128, SEQ / 128, BB);
        gemm_f16<<<grid, 256, SMH>>>(pf, vt, o, SEQ, SEQ, SEQ, DIM,
                                     sS, sVT, sQKV);
    }
    // 7: out = query + O @ Wo + bo (tf32 1-pass)
    {
        dim3 grid(DIM / 128, (BB * SEQ) / 128, 1);
        gemm_t32<4><<<grid, 256, SM1>>>(o, wot, out, bo, query,
                                        DIM, DIM, DIM, DIM, 0, 0, 0);
    }
}

// round 12
// speedup vs baseline: 1.8470x; 1.1609x over previous
#include <cuda_runtime.h>
#include <cuda_bf16.h>
#include <cuda_fp16.h>
#include <cstdint>

// ===========================================================================
// AxisAttention: bf16x3 (m16n8k16, 256thr/IT4/occ2) for q/k proj + QK^T;
// fp16 single-pass for PV; tf32 single-pass for v-proj, out-proj.
// All multi-term epilogues staged through smem for coalesced stores.
// B=4, N=2048, D=DA=512.
// ===========================================================================

constexpr int BB  = 4;
constexpr int SEQ = 2048;
constexpr int DIM = 512;
constexpr float SCALE_F = 22.62741699796952f;

constexpr size_t BND = (size_t)BB * SEQ * DIM;

// ---------------- device global scratch -------------------------------------
__device__ __nv_bfloat16 g_in_bh[2 * BND];
__device__ __nv_bfloat16 g_in_bl[2 * BND];
__device__ float         g_kv_t32[BND];
__device__ __nv_bfloat16 g_qk_bh[2 * BND];
__device__ __nv_bfloat16 g_qk_bl[2 * BND];
__device__ __half g_vt[(size_t)BB * DIM * SEQ];
__device__ float  g_s[(size_t)BB * SEQ * SEQ];
__device__ __half g_pf[(size_t)BB * SEQ * SEQ];
__device__ float  g_o[BND];
__device__ __nv_bfloat16 g_wqk_bh[2 * DIM * DIM];
__device__ __nv_bfloat16 g_wqk_bl[2 * DIM * DIM];
__device__ float g_wvt[DIM * DIM];
__device__ float g_wot[DIM * DIM];

// ---------------- helpers ----------------------------------------------------
__device__ __forceinline__ uint32_t smem_u32(const void* p) {
    uint32_t a;
    asm("{ .reg .u64 t; cvta.to.shared.u64 t, %1; cvt.u32.u64 %0, t; }"
        : "=r"(a) : "l"(p));
    return a;
}
__device__ __forceinline__ float tf32_rna(float x) {
    uint32_t u;
    asm("cvt.rna.tf32.f32 %0, %1;" : "=r"(u) : "f"(x));
    return __uint_as_float(u);
}
__device__ __forceinline__ void cp16(uint32_t saddr, const void* g) {
    asm volatile("cp.async.cg.shared.global [%0], [%1], 16;"
                 :: "r"(saddr), "l"(g) : "memory");
}
__device__ __forceinline__ void cp_commit() {
    asm volatile("cp.async.commit_group;" ::: "memory");
}
template <int N>
__device__ __forceinline__ void cp_wait() {
    asm volatile("cp.async.wait_group %0;" :: "n"(N) : "memory");
}

__device__ __forceinline__ int permk(int k) {
    const int lo = k & 7;
    return (k & ~15) | ((k & 8) + 2 * (lo & 3) + (lo >> 2));
}
__device__ __forceinline__ int permkb(int k) {
    const int t = k & 15;
    const int q = (t & 7) >> 1, d = t & 1, e = t >> 3;
    return (k & ~15) | (4 * q + 2 * e + d);
}

__device__ __forceinline__ void mma8(float* c, float a0, float a1, float a2,
                                     float a3, float b0, float b1) {
    asm volatile(
        "mma.sync.aligned.m16n8k8.row.col.f32.tf32.tf32.f32 "
        "{%0,%1,%2,%3}, {%4,%5,%6,%7}, {%8,%9}, {%0,%1,%2,%3};"
        : "+f"(c[0]), "+f"(c[1]), "+f"(c[2]), "+f"(c[3])
        : "r"(__float_as_uint(a0)), "r"(__float_as_uint(a1)),
          "r"(__float_as_uint(a2)), "r"(__float_as_uint(a3)),
          "r"(__float_as_uint(b0)), "r"(__float_as_uint(b1)));
}
__device__ __forceinline__ void mma16(float* c, uint32_t a0, uint32_t a1,
                                      uint32_t a2, uint32_t a3,
                                      uint32_t b0, uint32_t b1) {
    asm volatile(
        "mma.sync.aligned.m16n8k16.row.col.f32.bf16.bf16.f32 "
        "{%0,%1,%2,%3}, {%4,%5,%6,%7}, {%8,%9}, {%0,%1,%2,%3};"
        : "+f"(c[0]), "+f"(c[1]), "+f"(c[2]), "+f"(c[3])
        : "r"(a0), "r"(a1), "r"(a2), "r"(a3), "r"(b0), "r"(b1));
}
__device__ __forceinline__ void mma16h(float* c, uint32_t a0, uint32_t a1,
                                       uint32_t a2, uint32_t a3,
                                       uint32_t b0, uint32_t b1) {
    asm volatile(
        "mma.sync.aligned.m16n8k16.row.col.f32.f16.f16.f32 "
        "{%0,%1,%2,%3}, {%4,%5,%6,%7}, {%8,%9}, {%0,%1,%2,%3};"
        : "+f"(c[0]), "+f"(c[1]), "+f"(c[2]), "+f"(c[3])
        : "r"(a0), "r"(a1), "r"(a2), "r"(a3), "r"(b0), "r"(b1));
}
__device__ __forceinline__ uint32_t f2u(float x) { return __float_as_uint(x); }

// ===========================================================================
// bf16 split GEMM (hh+hl+lh): CTA 128x128, 256 thr occ 2, warp 64x32 (IT=4),
// K-chunk 32, double buffer. SMEM row: [hi 64B | lo 64B | pad 32B] = 160B.
// EPI 0: bf16 hi/lo split + bias, staged smem epilogue.
// EPI 2: alpha-scaled fp32 (permkb cols), staged smem epilogue.
// ===========================================================================
template <int EPI>
__global__ void __launch_bounds__(256, 2) gemm_bf16(
    const __nv_bfloat16* __restrict__ Ahi, const __nv_bfloat16* __restrict__ Alo,
    const __nv_bfloat16* __restrict__ Bhi, const __nv_bfloat16* __restrict__ Blo,
    void* __restrict__ Cp, void* __restrict__ C2p,
    const float* __restrict__ bias, const float* __restrict__ bias2,
    int K, int lda, int ldb, int ldc,
    size_t sA, size_t sB, size_t sC, float alpha)
{
    constexpr int IT = 4, WN = 4;
    constexpr int ROWB  = 160;
    constexpr int TILEB = 128 * ROWB;     // 20480
    constexpr int STAGEB = 2 * TILEB;     // 40960

    extern __shared__ char smc[];
    const uint32_t sb = smem_u32(smc);

    const int tid    = threadIdx.x;
    const int lane   = tid & 31;
    const int wid    = tid >> 5;
    const int warp_m = wid >> 2;      // 0..1
    const int warp_n = wid & 3;       // 0..3
    const int q      = lane & 3;
    const int n0 = blockIdx.x * 128;
    const int m0 = blockIdx.y * 128;
    const int z  = blockIdx.z;

    const float* bias_z = (EPI == 0 && z == 1) ? bias2 : bias;

    const __nv_bfloat16* A0 = Ahi + (size_t)z * sA + (size_t)m0 * lda;
    const __nv_bfloat16* A1 = Alo + (size_t)z * sA + (size_t)m0 * lda;
    const __nv_bfloat16* B0 = Bhi + (size_t)z * sB + (size_t)n0 * ldb;
    const __nv_bfloat16* B1 = Blo + (size_t)z * sB + (size_t)n0 * ldb;

    float acc[IT][WN][4];
#pragma unroll
    for (int i = 0; i < IT; i++)
#pragma unroll
        for (int j = 0; j < WN; j++)
#pragma unroll
            for (int l = 0; l < 4; l++) acc[i][j][l] = 0.0f;

    const int nch = K / 32;

    auto load_stage = [&](int buf, int c) {
        const uint32_t st = sb + (uint32_t)buf * STAGEB;
#pragma unroll
        for (int i = 0; i < 8; i++) {
            const int idx = tid + i * 256;          // 0..2047
            const int tile = idx >> 10;
            const int w    = idx & 1023;
            const int row  = w >> 3;
            const int h    = (w >> 2) & 1;
            const int cc   = w & 3;
            const __nv_bfloat16* src =
                tile ? (h ? B1 : B0) : (h ? A1 : A0);
            const int ld = tile ? ldb : lda;
            cp16(st + (uint32_t)(tile * TILEB + row * ROWB + h * 64 + cc * 16),
                 src + (size_t)row * ld + c * 32 + cc * 8);
        }
    };

    load_stage(0, 0);
    cp_commit();

    const int arow0 = warp_m * 64 + (lane >> 2);
    const int bcol0 = warp_n * 32 + (lane >> 2);

    for (int c = 0; c < nch; c++) {
        if (c + 1 < nch) {
            load_stage((c + 1) & 1, c + 1);
            cp_commit();
            cp_wait<1>();
        } else {
            cp_wait<0>();
        }
        __syncthreads();

        const char* stg = smc + (size_t)(c & 1) * STAGEB;
        const char* Ab  = stg;
        const char* Bb  = stg + TILEB;

#pragma unroll
        for (int b = 0; b < 2; b++) {
            const int kb = b * 32 + 8 * q;
            // hi*hi
            float2 Ah0[IT], Ah1[IT];
#pragma unroll
            for (int i = 0; i < IT; i++) {
                const int row = arow0 + i * 16;
                Ah0[i] = *reinterpret_cast<const float2*>(Ab + row * ROWB + kb);
                Ah1[i] = *reinterpret_cast<const float2*>(Ab + (row + 8) * ROWB + kb);
            }
            float2 Bh[WN];
#pragma unroll
            for (int j = 0; j < WN; j++)
                Bh[j] = *reinterpret_cast<const float2*>(
                    Bb + (bcol0 + j * 8) * ROWB + kb);
#pragma unroll
            for (int i = 0; i < IT; i++)
#pragma unroll
                for (int j = 0; j < WN; j++)
                    mma16(acc[i][j], f2u(Ah0[i].x), f2u(Ah1[i].x),
                          f2u(Ah0[i].y), f2u(Ah1[i].y), f2u(Bh[j].x), f2u(Bh[j].y));
            // hi*lo
            float2 Bl[WN];
#pragma unroll
            for (int j = 0; j < WN; j++)
                Bl[j] = *reinterpret_cast<const float2*>(
                    Bb + (bcol0 + j * 8) * ROWB + 64 + kb);
#pragma unroll
            for (int i = 0; i < IT; i++)
#pragma unroll
                for (int j = 0; j < WN; j++)
                    mma16(acc[i][j], f2u(Ah0[i].x), f2u(Ah1[i].x),
                          f2u(Ah0[i].y), f2u(Ah1[i].y), f2u(Bl[j].x), f2u(Bl[j].y));
            // lo*hi
            float2 Al0[IT], Al1[IT];
#pragma unroll
            for (int i = 0; i < IT; i++) {
                const int row = arow0 + i * 16;
                Al0[i] = *reinterpret_cast<const float2*>(Ab + row * ROWB + 64 + kb);
                Al1[i] = *reinterpret_cast<const float2*>(Ab + (row + 8) * ROWB + 64 + kb);
            }
#pragma unroll
            for (int i = 0; i < IT; i++)
#pragma unroll
                for (int j = 0; j < WN; j++)
                    mma16(acc[i][j], f2u(Al0[i].x), f2u(Al1[i].x),
                          f2u(Al0[i].y), f2u(Al1[i].y), f2u(Bh[j].x), f2u(Bh[j].y));
        }
        __syncthreads();
    }

    // ---------------- staged epilogues ----------------
    if (EPI == 0) {
        __nv_bfloat16* sh = reinterpret_cast<__nv_bfloat16*>(smc);
        __nv_bfloat16* sl = sh + 128 * 128;
#pragma unroll
        for (int i = 0; i < IT; i++) {
#pragma unroll
            for (int j = 0; j < WN; j++) {
                const float* a4 = acc[i][j];
                const int lr = warp_m * 64 + i * 16 + (lane >> 2);
                const int lc = warp_n * 32 + j * 8 + 2 * q;
                const float bx = bias_z[n0 + lc], by = bias_z[n0 + lc + 1];
                const int p0 = permkb(lc), p1 = permkb(lc + 1);
                const float v[4] = {a4[0] + bx, a4[1] + by, a4[2] + bx, a4[3] + by};
                const int rr[4] = {lr, lr, lr + 8, lr + 8};
                const int pp[4] = {p0, p1, p0, p1};
#pragma unroll
                for (int u = 0; u < 4; u++) {
                    const __nv_bfloat16 h = __float2bfloat16(v[u]);
                    sh[rr[u] * 128 + pp[u]] = h;
                    sl[rr[u] * 128 + pp[u]] =
                        __float2bfloat16(v[u] - __bfloat162float(h));
                }
            }
        }
        __syncthreads();
        __nv_bfloat16* Cz  = (__nv_bfloat16*)Cp  + (size_t)z * sC;
        __nv_bfloat16* C2z = (__nv_bfloat16*)C2p + (size_t)z * sC;
#pragma unroll
        for (int t = 0; t < 8; t++) {
            const int idx = tid + t * 256;         // 0..2047
            const int row = idx >> 4;
            const int c16 = idx & 15;
            *reinterpret_cast<uint4*>(Cz + (size_t)(m0 + row) * ldc + n0 + c16 * 8) =
                *reinterpret_cast<const uint4*>(sh + row * 128 + c16 * 8);
            *reinterpret_cast<uint4*>(C2z + (size_t)(m0 + row) * ldc + n0 + c16 * 8) =
                *reinterpret_cast<const uint4*>(sl + row * 128 + c16 * 8);
        }
    } else {
        float* ss = reinterpret_cast<float*>(smc);   // 128x128 fp32 = 64KB
#pragma unroll
        for (int i = 0; i < IT; i++) {
#pragma unroll
            for (int j = 0; j < WN; j++) {
                const float* a4 = acc[i][j];
                const int lr = warp_m * 64 + i * 16 + (lane >> 2);
                const int lc = warp_n * 32 + j * 8 + 2 * q;
                const int p0 = permkb(lc), p1 = permkb(lc + 1);
                ss[lr * 128 + p0]       = alpha * a4[0];
                ss[lr * 128 + p1]       = alpha * a4[1];
                ss[(lr + 8) * 128 + p0] = alpha * a4[2];
                ss[(lr + 8) * 128 + p1] = alpha * a4[3];
            }
        }
        __syncthreads();
        float* Cz = (float*)Cp + (size_t)z * sC;
#pragma unroll
        for (int t = 0; t < 16; t++) {
            const int idx = tid + t * 256;         // 0..4095
            const int row = idx >> 5;
            const int c8  = idx & 31;
            *reinterpret_cast<uint4*>(Cz + (size_t)(m0 + row) * ldc + n0 + c8 * 4) =
                *reinterpret_cast<const uint4*>(ss + row * 128 + c8 * 4);
        }
    }
}

// ===========================================================================
// fp16 single-pass GEMM (PV): CTA 128x128, 256 thr occ 2, warp 64x32,
// K-chunk 32, ROWB=80. Output fp32 tf32-rounded, permk cols.
// ===========================================================================
__global__ void __launch_bounds__(256, 2) gemm_f16(
    const __half* __restrict__ A, const __half* __restrict__ B,
    float* __restrict__ C,
    int K, int lda, int ldb, int ldc,
    size_t sA, size_t sB, size_t sC)
{
    constexpr int IT = 4;
    constexpr int ROWB  = 80;
    constexpr int TILEB = 128 * ROWB;
    constexpr int STAGEB = 2 * TILEB;

    extern __shared__ char smc[];
    const uint32_t sb = smem_u32(smc);

    const int tid    = threadIdx.x;
    const int lane   = tid & 31;
    const int wid    = tid >> 5;
    const int warp_m = wid >> 2;
    const int warp_n = wid & 3;
    const int q      = lane & 3;
    const int n0 = blockIdx.x * 128;
    const int m0 = blockIdx.y * 128;
    const int z  = blockIdx.z;

    const __half* A0 = A + (size_t)z * sA + (size_t)m0 * lda;
    const __half* B0 = B + (size_t)z * sB + (size_t)n0 * ldb;

    float acc[IT][4][4];
#pragma unroll
    for (int i = 0; i < IT; i++)
#pragma unroll
        for (int j = 0; j < 4; j++)
#pragma unroll
            for (int l = 0; l < 4; l++) acc[i][j][l] = 0.0f;

    const int nch = K / 32;

    auto load_stage = [&](int buf, int c) {
        const uint32_t st = sb + (uint32_t)buf * STAGEB;
#pragma unroll
        for (int i = 0; i < 4; i++) {
            const int idx = tid + i * 256;
            const int tile = idx >> 9;
            const int w    = idx & 511;
            const int row  = w >> 2;
            const int cc   = w & 3;
            const __half* src = tile ? B0 : A0;
            const int ld = tile ? ldb : lda;
            cp16(st + (uint32_t)(tile * TILEB + row * ROWB + cc * 16),
                 src + (size_t)row * ld + c * 32 + cc * 8);
        }
    };

    load_stage(0, 0);
    cp_commit();

    const int arow0 = warp_m * 64 + (lane >> 2);
    const int bcol0 = warp_n * 32 + (lane >> 2);

    for (int c = 0; c < nch; c++) {
        if (c + 1 < nch) {
            load_stage((c + 1) & 1, c + 1);
            cp_commit();
            cp_wait<1>();
        } else {
            cp_wait<0>();
        }
        __syncthreads();

        const char* stg = smc + (size_t)(c & 1) * STAGEB;
        const char* Ab  = stg;
        const char* Bb  = stg + TILEB;

#pragma unroll
        for (int b = 0; b < 2; b++) {
            const int kb = b * 32 + 8 * q;
            float2 a0[IT], a1[IT], b0[4];
#pragma unroll
            for (int i = 0; i < IT; i++) {
                const int row = arow0 + i * 16;
                a0[i] = *reinterpret_cast<const float2*>(Ab + row * ROWB + kb);
                a1[i] = *reinterpret_cast<const float2*>(Ab + (row + 8) * ROWB + kb);
            }
#pragma unroll
            for (int j = 0; j < 4; j++)
                b0[j] = *reinterpret_cast<const float2*>(
                    Bb + (bcol0 + j * 8) * ROWB + kb);
#pragma unroll
            for (int i = 0; i < IT; i++)
#pragma unroll
                for (int j = 0; j < 4; j++)
                    mma16h(acc[i][j], f2u(a0[i].x), f2u(a1[i].x),
                           f2u(a0[i].y), f2u(a1[i].y), f2u(b0[j].x), f2u(b0[j].y));
        }
        __syncthreads();
    }

    float* Cz = C + (size_t)z * sC;
#pragma unroll
    for (int i = 0; i < IT; i++) {
#pragma unroll
        for (int j = 0; j < 4; j++) {
            const float* a4 = acc[i][j];
            const int r0 = m0 + warp_m * 64 + i * 16 + (lane >> 2);
            const int c0 = n0 + warp_n * 32 + j * 8 + 2 * q;
            const int p0 = permk(c0), p1 = permk(c0 + 1);
            Cz[(size_t)r0 * ldc + p0]       = tf32_rna(a4[0]);
            Cz[(size_t)r0 * ldc + p1]       = tf32_rna(a4[1]);
            Cz[(size_t)(r0 + 8) * ldc + p0] = tf32_rna(a4[2]);
            Cz[(size_t)(r0 + 8) * ldc + p1] = tf32_rna(a4[3]);
        }
    }
}

// ===========================================================================
// tf32 1-pass GEMM: CTA 128x128, 256 thr occ 2, warp 64x32, K-chunk 32.
// EPI: 1=transposed fp16 VT+bias (permkb seq), 4=bias+residual fp32.
// ===========================================================================
constexpr int LDW    = 40;
constexpr int TILE_F = 128 * LDW;
constexpr int TILE_B = TILE_F * 4;

__device__ __forceinline__ void load_tile32(
    uint32_t sbase, const float* __restrict__ g, int ld, int tid)
{
#pragma unroll
    for (int i = 0; i < 4; i++) {
        const int f  = tid + i * 256;
        const int r  = f >> 3;
        const int c4 = (f & 7) << 2;
        cp16(sbase + (uint32_t)(r * LDW + c4) * 4, g + (size_t)r * ld + c4);
    }
}

template <int EPI>
__global__ void __launch_bounds__(256, 2) gemm_t32(
    const float* __restrict__ A, const float* __restrict__ B,
    float* __restrict__ C,
    const float* __restrict__ bias, const float* __restrict__ resid,
    int K, int lda, int ldb, int ldc,
    size_t sA, size_t sB, size_t sC)
{
    constexpr int IT = 4;
    extern __shared__ float smf[];
    const uint32_t sb = smem_u32(smf);

    const int tid    = threadIdx.x;
    const int lane   = tid & 31;
    const int wid    = tid >> 5;
    const int warp_m = wid >> 2;
    const int warp_n = wid & 3;
    const int n0 = blockIdx.x * 128;
    const int m0 = blockIdx.y * 128;
    const int z  = blockIdx.z;

    const float* A0 = A + (size_t)z * sA + (size_t)m0 * lda;
    const float* B0 = B + (size_t)z * sB + (size_t)n0 * ldb;

    float acc[IT][4][4];
#pragma unroll
    for (int i = 0; i < IT; i++)
#pragma unroll
        for (int j = 0; j < 4; j++)
#pragma unroll
            for (int l = 0; l < 4; l++) acc[i][j][l] = 0.0f;

    const int nch = K / 32;

    auto load_stage = [&](int buf, int c) {
        const uint32_t st = sb + (uint32_t)buf * 2 * TILE_B;
        load_tile32(st,          A0 + c * 32, lda, tid);
        load_tile32(st + TILE_B, B0 + c * 32, ldb, tid);
    };

    load_stage(0, 0);
    cp_commit();

    const int arow0 = warp_m * 64 + (lane >> 2);
    const int bcol0 = warp_n * 32 + (lane >> 2);
    const int kq2   = 2 * (lane & 3);

    for (int c = 0; c < nch; c++) {
        if (c + 1 < nch) {
            load_stage((c + 1) & 1, c + 1);
            cp_commit();
            cp_wait<1>();
        } else {
            cp_wait<0>();
        }
        __syncthreads();

        const float* st  = smf + (size_t)(c & 1) * 2 * TILE_F;
        const float* Ath = st;
        const float* Bth = st + TILE_F;

#pragma unroll
        for (int s = 0; s < 4; s++) {
            const int ko = s * 8 + kq2;
            float2 a0[IT], a1[IT], b0[4];
#pragma unroll
            for (int i = 0; i < IT; i++) {
                a0[i] = *reinterpret_cast<const float2*>(
                    Ath + (size_t)(arow0 + i * 16) * LDW + ko);
                a1[i] = *reinterpret_cast<const float2*>(
                    Ath + (size_t)(arow0 + i * 16 + 8) * LDW + ko);
            }
#pragma unroll
            for (int j = 0; j < 4; j++)
                b0[j] = *reinterpret_cast<const float2*>(
                    Bth + (size_t)(bcol0 + j * 8) * LDW + ko);
#pragma unroll
            for (int i = 0; i < IT; i++)
#pragma unroll
                for (int j = 0; j < 4; j++)
                    mma8(acc[i][j], a0[i].x, a1[i].x, a0[i].y, a1[i].y,
                         b0[j].x, b0[j].y);
        }
        __syncthreads();
    }

    float* Cz = C + (size_t)z * sC;
#pragma unroll
    for (int i = 0; i < IT; i++) {
#pragma unroll
        for (int j = 0; j < 4; j++) {
            const float* a4 = acc[i][j];
            const int r0 = m0 + warp_m * 64 + i * 16 + (lane >> 2);
            const int c0 = n0 + warp_n * 32 + j * 8 + 2 * (lane & 3);
            if (EPI == 1) {
                __half* Cv = (__half*)C;
                const float bx = bias[c0], by = bias[c0 + 1];
                const int b0i = r0 >> 11,        sx0 = permkb(r0 & (SEQ - 1));
                const int b1i = (r0 + 8) >> 11,  sx1 = permkb((r0 + 8) & (SEQ - 1));
                __half* p0 = Cv + (size_t)b0i * DIM * SEQ;
                __half* p1 = Cv + (size_t)b1i * DIM * SEQ;
                p0[(size_t)c0 * SEQ + sx0]       = __float2half(a4[0] + bx);
                p0[(size_t)(c0 + 1) * SEQ + sx0] = __float2half(a4[1] + by);
                p1[(size_t)c0 * SEQ + sx1]       = __float2half(a4[2] + bx);
                p1[(size_t)(c0 + 1) * SEQ + sx1] = __float2half(a4[3] + by);
            } else {
                const float bx = bias[c0], by = bias[c0 + 1];
                const float2 rs0 = *reinterpret_cast<const float2*>(
                    &resid[(size_t)r0 * ldc + c0]);
                const float2 rs1 = *reinterpret_cast<const float2*>(
                    &resid[(size_t)(r0 + 8) * ldc + c0]);
                float2 v0, v1;
                v0.x = a4[0] + bx + rs0.x; v0.y = a4[1] + by + rs0.y;
                v1.x = a4[2] + bx + rs1.x; v1.y = a4[3] + by + rs1.y;
                *reinterpret_cast<float2*>(&Cz[(size_t)r0 * ldc + c0]) = v0;
                *reinterpret_cast<float2*>(&Cz[(size_t)(r0 + 8) * ldc + c0]) = v1;
            }
        }
    }
}

// ---------------- prep kernels ----------------------------------------------
__global__ void split_all(const float4* __restrict__ q, const float4* __restrict__ kv,
                          __nv_bfloat16* __restrict__ dh,
                          __nv_bfloat16* __restrict__ dl,
                          float* __restrict__ kv32, int n4)
{
    int id = blockIdx.x * 256 + threadIdx.x;
    if (id >= 2 * n4) return;
    const bool is_kv = (id >= n4);
    const float4 v = is_kv ? kv[id - n4] : q[id];
    const int e0 = id * 4;
    const int base = e0 & ~511;
    const float vv[4] = {v.x, v.y, v.z, v.w};
#pragma unroll
    for (int u = 0; u < 4; u++) {
        const int k = (e0 + u) & 511;
        const float x = vv[u];
        const __nv_bfloat16 h = __float2bfloat16(x);
        const int pb = permkb(k);
        dh[base + pb] = h;
        dl[base + pb] = __float2bfloat16(x - __bfloat162float(h));
        if (is_kv) kv32[(base - (int)BND) + permk(k)] = tf32_rna(x);
    }
}

__global__ void wprep_all(const float* __restrict__ Wq, const float* __restrict__ Wk,
                          const float* __restrict__ Wv, const float* __restrict__ Wo,
                          __nv_bfloat16* __restrict__ wbh,
                          __nv_bfloat16* __restrict__ wbl,
                          float* __restrict__ vh, float* __restrict__ oh)
{
    const int idx = blockIdx.x * 256 + threadIdx.x;
    const int wsel = blockIdx.y;
    const int n = idx & 511;
    const int k = idx >> 9;
    if (wsel < 2) {
        const float w = (wsel ? Wk : Wq)[(size_t)k * DIM + n];
        const __nv_bfloat16 h = __float2bfloat16(w);
        const size_t dst = (size_t)wsel * DIM * DIM + (size_t)n * DIM + permkb(k);
        wbh[dst] = h;
        wbl[dst] = __float2bfloat16(w - __bfloat162float(h));
    } else {
        const float w = (wsel == 2 ? Wv : Wo)[(size_t)k * DIM + n];
        float* T = (wsel == 2) ? vh : oh;
        T[(size_t)n * DIM + permk(k)] = tf32_rna(w);
    }
}

__global__ void __launch_bounds__(256) softmax_rows(const float* __restrict__ S,
                                                    __half* __restrict__ P)
{
    const size_t row = blockIdx.x;
    const float* p = S + row * (size_t)SEQ;
    __half* po = P + row * (size_t)SEQ;
    const int t = threadIdx.x;
    float vals[8];
    float m = -3.402823466e38f;
#pragma unroll
    for (int i = 0; i < 8; i++) { vals[i] = p[t + i * 256]; m = fmaxf(m, vals[i]); }
    __shared__ float red[256];
    red[t] = m; __syncthreads();
#pragma unroll
    for (int s = 128; s > 0; s >>= 1) { if (t < s) red[t] = fmaxf(red[t], red[t+s]); __syncthreads(); }
    m = red[0]; __syncthreads();
    float sum = 0.0f;
#pragma unroll
    for (int i = 0; i < 8; i++) { vals[i] = __expf(vals[i] - m); sum += vals[i]; }
    red[t] = sum; __syncthreads();
#pragma unroll
    for (int s = 128; s > 0; s >>= 1) { if (t < s) red[t] += red[t+s]; __syncthreads(); }
    const float inv = 1.0f / red[0];
#pragma unroll
    for (int i = 0; i < 8; i++) po[t + i * 256] = __float2half(vals[i] * inv);
}

// ---------------- launcher --------------------------------------------------
extern "C" void kernel_launch(void* const* d_in, const int* in_sizes, int n_in,
                              void* d_out, int out_size)
{
    (void)in_sizes; (void)n_in; (void)out_size;
    const float* query     = (const float*)d_in[0];
    const float* key_value = (const float*)d_in[1];
    const float* Wq = (const float*)d_in[2];
    const float* bq = (const float*)d_in[3];
    const float* Wk = (const float*)d_in[4];
    const float* bk = (const float*)d_in[5];
    const float* Wv = (const float*)d_in[6];
    const float* bv = (const float*)d_in[7];
    const float* Wo = (const float*)d_in[8];
    const float* bo = (const float*)d_in[9];
    float* out = (float*)d_out;

    __nv_bfloat16 *in_bh, *in_bl, *qk_bh, *qk_bl, *wbh, *wbl;
    __half *vt, *pf;
    float *kv_t32, *s, *o, *wvt, *wot;
    cudaGetSymbolAddress((void**)&in_bh,  g_in_bh);
    cudaGetSymbolAddress((void**)&in_bl,  g_in_bl);
    cudaGetSymbolAddress((void**)&kv_t32, g_kv_t32);
    cudaGetSymbolAddress((void**)&qk_bh,  g_qk_bh);
    cudaGetSymbolAddress((void**)&qk_bl,  g_qk_bl);
    cudaGetSymbolAddress((void**)&vt,     g_vt);
    cudaGetSymbolAddress((void**)&s,      g_s);
    cudaGetSymbolAddress((void**)&pf,     g_pf);
    cudaGetSymbolAddress((void**)&o,      g_o);
    cudaGetSymbolAddress((void**)&wbh,    g_wqk_bh);
    cudaGetSymbolAddress((void**)&wbl,    g_wqk_bl);
    cudaGetSymbolAddress((void**)&wvt,    g_wvt);
    cudaGetSymbolAddress((void**)&wot,    g_wot);

    constexpr int SMB = 2 * 2 * 128 * 160;   // 81920 B
    constexpr int SMH = 2 * 2 * 128 * 80;    // 40960 B
    constexpr int SM1 = 2 * 2 * TILE_B;      // 81920 B
    cudaFuncSetAttribute(gemm_bf16<0>, cudaFuncAttributeMaxDynamicSharedMemorySize, SMB);
    cudaFuncSetAttribute(gemm_bf16<2>, cudaFuncAttributeMaxDynamicSharedMemorySize, SMB);
    cudaFuncSetAttribute(gemm_f16, cudaFuncAttributeMaxDynamicSharedMemorySize, SMH);
    cudaFuncSetAttribute(gemm_t32<1>, cudaFuncAttributeMaxDynamicSharedMemorySize, SM1);
    cudaFuncSetAttribute(gemm_t32<4>, cudaFuncAttributeMaxDynamicSharedMemorySize, SM1);

    const size_t sQKV = (size_t)SEQ * DIM;
    const size_t sS   = (size_t)SEQ * SEQ;
    const size_t sVT  = (size_t)DIM * SEQ;
    const int n4 = (int)(BND / 4);

    split_all<<<(2 * n4) / 256, 256>>>((const float4*)query,
        (const float4*)key_value, in_bh, in_bl, kv_t32, n4);
    {
        dim3 g((DIM * DIM) / 256, 4);
        wprep_all<<<g, 256>>>(Wq, Wk, Wv, Wo, wbh, wbl, wvt, wot);
    }
    // v projection -> fp16 VT
    {
        dim3 grid(DIM / 128, (BB * SEQ) / 128, 1);
        gemm_t32<1><<<grid, 256, SM1>>>(kv_t32, wvt, (float*)vt, bv, nullptr,
                                        DIM, DIM, DIM, 0, 0, 0, 0);
    }
    // q,k projections fused
    {
        dim3 grid(DIM / 128, (BB * SEQ) / 128, 2);
        gemm_bf16<0><<<grid, 256, SMB>>>(in_bh, in_bl, wbh, wbl,
            qk_bh, qk_bl, bq, bk, DIM, DIM, DIM, DIM,
            BND, (size_t)DIM * DIM, BND, 1.0f);
    }
    // S = sqrt(512) * q @ k^T
    {
        dim3 grid(SEQ / 128, SEQ / 128, BB);
        gemm_bf16<2><<<grid, 256, SMB>>>(qk_bh, qk_bl, qk_bh + BND, qk_bl + BND,
            s, nullptr, nullptr, nullptr, DIM, DIM, DIM, SEQ,
            sQKV, sQKV, sS, SCALE_F);
    }
    softmax_rows<<<BB * SEQ, 256>>>(s, pf);
    // O = P @ V (fp16)
    {
        dim3 grid(DIM / 128, SEQ / 128, BB);
        gemm_f16<<<grid, 256, SMH>>>(pf, vt, o, SEQ, SEQ, SEQ, DIM,
                                     sS, sVT, sQKV);
    }
    // out = query + O @ Wo + bo
    {
        dim3 grid(DIM / 128, (BB * SEQ) / 128, 1);
        gemm_t32<4><<<grid, 256, SM1>>>(o, wot, out, bo, query,
                                        DIM, DIM, DIM, DIM, 0, 0, 0);
    }
}